// round 1
// baseline (speedup 1.0000x reference)
#include <cuda_runtime.h>

// Problem constants
#define U_NODES 200000
#define F_DIM   256
#define E_DIM   128
#define B_ROWS  20000
#define K_SAMP  33
#define BN_EPS  1e-5f

// GEMM tiling
#define TM 128
#define TK 8
#define NTILES ((U_NODES + TM - 1) / TM)   // 1563
#define NKC (F_DIM / TK)                   // 32

// Scratch (static device globals; no runtime allocation)
__device__ float g_h[(size_t)U_NODES * E_DIM];          // 102.4 MB pre-activation h
__device__ float g_part[NTILES * 2 * E_DIM];            // per-tile column sum / sumsq
__device__ float g_ab[2 * E_DIM];                       // a[e] = gamma*rstd, c[e] = beta - mu*a

// ---------------------------------------------------------------------------
// Kernel 1: h = features @ W + b   (+ per-tile column sum/sumsq partials)
// CTA: 128 rows x 128 cols (full E), K-chunks of 8, double-buffered smem,
// 256 threads, each computing an 8x8 microtile.
// ---------------------------------------------------------------------------
__global__ void __launch_bounds__(256, 2)
gemm_stats_kernel(const float* __restrict__ A,      // [U, F]
                  const float* __restrict__ W,      // [F, E]
                  const float* __restrict__ bias)   // [E]
{
    __shared__ float As[2][TK][TM];     // k-major A tile (transposed on store)
    __shared__ float Bs[2][TK][E_DIM];  // k-major B tile

    const int tid   = threadIdx.x;
    const int tileM = blockIdx.x;
    const int row0  = tileM * TM;

    // global-load assignments
    const int aRow = tid >> 1;          // 0..127
    const int aCol = (tid & 1) << 2;    // 0 or 4
    const int bRow = tid >> 5;          // 0..7
    const int bCol = (tid & 31) << 2;   // 0..124

    // microtile assignment
    const int tx = tid & 15;            // col group
    const int ty = tid >> 4;            // row group

    const bool aValid = (row0 + aRow) < U_NODES;
    const float* Aptr = A + (size_t)(row0 + aRow) * F_DIM + aCol;

    float acc[8][8];
#pragma unroll
    for (int i = 0; i < 8; i++)
#pragma unroll
        for (int j = 0; j < 8; j++) acc[i][j] = 0.f;

    // prefetch chunk 0 into buffer 0
    {
        float4 av = make_float4(0.f, 0.f, 0.f, 0.f);
        if (aValid) av = *(const float4*)(Aptr);
        As[0][aCol + 0][aRow] = av.x;
        As[0][aCol + 1][aRow] = av.y;
        As[0][aCol + 2][aRow] = av.z;
        As[0][aCol + 3][aRow] = av.w;
        float4 wv = *(const float4*)(W + (size_t)bRow * E_DIM + bCol);
        *(float4*)&Bs[0][bRow][bCol] = wv;
    }
    __syncthreads();

    for (int kc = 0; kc < NKC; kc++) {
        const int cur = kc & 1;
        float4 av = make_float4(0.f, 0.f, 0.f, 0.f);
        float4 wv;
        const bool have = (kc + 1) < NKC;
        if (have) {
            const int k0 = (kc + 1) * TK;
            if (aValid) av = *(const float4*)(Aptr + k0);
            wv = *(const float4*)(W + (size_t)(k0 + bRow) * E_DIM + bCol);
        }

#pragma unroll
        for (int k = 0; k < TK; k++) {
            float4 a0 = *(const float4*)&As[cur][k][ty * 8];
            float4 a1 = *(const float4*)&As[cur][k][ty * 8 + 4];
            float4 b0 = *(const float4*)&Bs[cur][k][tx * 8];
            float4 b1 = *(const float4*)&Bs[cur][k][tx * 8 + 4];
            float af[8] = {a0.x, a0.y, a0.z, a0.w, a1.x, a1.y, a1.z, a1.w};
            float bf[8] = {b0.x, b0.y, b0.z, b0.w, b1.x, b1.y, b1.z, b1.w};
#pragma unroll
            for (int i = 0; i < 8; i++)
#pragma unroll
                for (int j = 0; j < 8; j++)
                    acc[i][j] = fmaf(af[i], bf[j], acc[i][j]);
        }

        if (have) {
            const int nb = cur ^ 1;
            As[nb][aCol + 0][aRow] = av.x;
            As[nb][aCol + 1][aRow] = av.y;
            As[nb][aCol + 2][aRow] = av.z;
            As[nb][aCol + 3][aRow] = av.w;
            *(float4*)&Bs[nb][bRow][bCol] = wv;
        }
        __syncthreads();
    }

    // epilogue: add bias
    float bj[8];
#pragma unroll
    for (int j = 0; j < 8; j++) bj[j] = __ldg(bias + tx * 8 + j);
#pragma unroll
    for (int i = 0; i < 8; i++)
#pragma unroll
        for (int j = 0; j < 8; j++) acc[i][j] += bj[j];

    // store h rows (guard the last, partial tile)
    const int validRows = U_NODES - row0;   // >= 128 except last tile (64)
#pragma unroll
    for (int i = 0; i < 8; i++) {
        const int r = ty * 8 + i;
        if (r < validRows) {
            float* dst = g_h + (size_t)(row0 + r) * E_DIM + tx * 8;
            float4 v0 = make_float4(acc[i][0], acc[i][1], acc[i][2], acc[i][3]);
            float4 v1 = make_float4(acc[i][4], acc[i][5], acc[i][6], acc[i][7]);
            *(float4*)(dst)     = v0;
            *(float4*)(dst + 4) = v1;
        }
    }

    // per-tile column sum / sumsq (deterministic tree via smem reuse)
    float* redS = &As[0][0][0];   // 2048 floats (8 KB)
    float* redQ = &Bs[0][0][0];   // 2048 floats (8 KB)
#pragma unroll
    for (int j = 0; j < 8; j++) {
        float s = 0.f, q = 0.f;
#pragma unroll
        for (int i = 0; i < 8; i++) {
            if (ty * 8 + i < validRows) {
                const float v = acc[i][j];
                s += v;
                q += v * v;
            }
        }
        redS[ty * E_DIM + tx * 8 + j] = s;
        redQ[ty * E_DIM + tx * 8 + j] = q;
    }
    __syncthreads();

    if (tid < E_DIM) {
        float s = 0.f, q = 0.f;
#pragma unroll
        for (int t = 0; t < 16; t++) {
            s += redS[t * E_DIM + tid];
            q += redQ[t * E_DIM + tid];
        }
        g_part[tileM * 2 * E_DIM + tid]          = s;
        g_part[tileM * 2 * E_DIM + E_DIM + tid]  = q;
    }
}

// ---------------------------------------------------------------------------
// Kernel 2: reduce partials -> a[e] = gamma*rsqrt(var+eps), c[e] = beta - mu*a
// ---------------------------------------------------------------------------
__global__ void finalize_stats_kernel(const float* __restrict__ gamma,
                                      const float* __restrict__ beta)
{
    const int e = threadIdx.x;   // 128 threads
    float s = 0.f, q = 0.f;
    for (int t = 0; t < NTILES; t++) {
        s += g_part[t * 2 * E_DIM + e];
        q += g_part[t * 2 * E_DIM + E_DIM + e];
    }
    const float mu  = s * (1.0f / U_NODES);
    const float var = q * (1.0f / U_NODES) - mu * mu;   // biased, matches jnp.var
    const float a   = gamma[e] * rsqrtf(var + BN_EPS);
    g_ab[e]         = a;
    g_ab[E_DIM + e] = beta[e] - mu * a;
}

// ---------------------------------------------------------------------------
// Kernel 3: out[b] = mean_k tanh(a*h[idx[b,k]] + c)
// one CTA per output row; BN+tanh fused into the gather (h stays in L2)
// ---------------------------------------------------------------------------
__global__ void __launch_bounds__(128)
gather_mean_kernel(const int* __restrict__ idx,   // [B, K] int32
                   float* __restrict__ out)       // [B, E]
{
    __shared__ int sidx[K_SAMP];
    const int b = blockIdx.x;
    const int e = threadIdx.x;
    if (e < K_SAMP) sidx[e] = idx[b * K_SAMP + e];
    __syncthreads();

    const float a = g_ab[e];
    const float c = g_ab[E_DIM + e];
    float accv = 0.f;
#pragma unroll
    for (int k = 0; k < K_SAMP; k++) {
        const float v = __ldg(g_h + (size_t)sidx[k] * E_DIM + e);
        // fast tanh: 1 - 2/(exp(2x)+1); clamp keeps exp finite, tanh saturated anyway
        float x = a * v + c;
        x = fminf(fmaxf(x, -15.f), 15.f);
        const float ex = __expf(2.f * x);
        accv += 1.f - __fdividef(2.f, ex + 1.f);
    }
    out[(size_t)b * E_DIM + e] = accv * (1.0f / K_SAMP);
}

// ---------------------------------------------------------------------------
extern "C" void kernel_launch(void* const* d_in, const int* in_sizes, int n_in,
                              void* d_out, int out_size)
{
    const float* features = (const float*)d_in[0];   // [U, F]
    const float* W        = (const float*)d_in[1];   // [F, E]
    const float* bias     = (const float*)d_in[2];   // [E]
    const float* gamma    = (const float*)d_in[3];   // [E]
    const float* beta     = (const float*)d_in[4];   // [E]
    const int*   sidx     = (const int*)d_in[5];     // [B, K] int32
    float*       out      = (float*)d_out;           // [B, E]

    gemm_stats_kernel<<<NTILES, 256>>>(features, W, bias);
    finalize_stats_kernel<<<1, E_DIM>>>(gamma, beta);
    gather_mean_kernel<<<B_ROWS, E_DIM>>>(sidx, out);
}

// round 3
// speedup vs baseline: 1.8807x; 1.8807x over previous
#include <cuda_runtime.h>
#include <cuda_bf16.h>
#include <cstdint>

// ---------------------------------------------------------------------------
// Problem constants
// ---------------------------------------------------------------------------
#define U_NODES 200000
#define F_DIM   256
#define E_DIM   128
#define B_ROWS  20000
#define K_SAMP  33
#define BN_EPS  1e-5f

#define TM      128
#define KC      64                        // K chunk (bf16 elems)
#define NCH     (F_DIM / KC)              // 4
#define NTILES  ((U_NODES + TM - 1) / TM) // 1563

// SMEM layout (bytes, dynamic)
#define OFF_BIAS   0
#define OFF_A      1024                       // 2 stages x (hi 16K + lo 16K)
#define OFF_W      (OFF_A + 65536)            // 2 stages x (hi 16K + lo 16K)
#define SMEM_TOTAL (OFF_W + 65536)            // 132096

// ---------------------------------------------------------------------------
// Device scratch
// ---------------------------------------------------------------------------
__device__ float g_h[(size_t)U_NODES * E_DIM];
__device__ float g_part[NTILES * 2 * E_DIM];
__device__ float g_ab[2 * E_DIM];
// W images: [K=256][N=128] bf16 row-major, 16B-column XOR-swizzled by (k&7)
__device__ __align__(16) __nv_bfloat16 g_wh[F_DIM * E_DIM];
__device__ __align__(16) __nv_bfloat16 g_wl[F_DIM * E_DIM];

// ---------------------------------------------------------------------------
// Helpers
// ---------------------------------------------------------------------------
__device__ __forceinline__ uint32_t smem_u32(const void* p) {
    uint32_t a;
    asm("{ .reg .u64 t; cvta.to.shared.u64 t, %1; cvt.u32.u64 %0, t; }"
        : "=r"(a) : "l"(p));
    return a;
}
__device__ __forceinline__ uint32_t packbf(__nv_bfloat16 a, __nv_bfloat16 b) {
    return ((uint32_t)__bfloat16_as_ushort(b) << 16) | __bfloat16_as_ushort(a);
}
__device__ __forceinline__ void sts128(uint32_t addr, uint32_t a, uint32_t b,
                                       uint32_t c, uint32_t d) {
    asm volatile("st.shared.v4.b32 [%0], {%1, %2, %3, %4};"
                 :: "r"(addr), "r"(a), "r"(b), "r"(c), "r"(d) : "memory");
}
__device__ __forceinline__ void cp16(uint32_t s, const void* g) {
    asm volatile("cp.async.cg.shared.global [%0], [%1], 16;"
                 :: "r"(s), "l"(g) : "memory");
}
__device__ __forceinline__ void cp_commit() {
    asm volatile("cp.async.commit_group;" ::: "memory");
}
__device__ __forceinline__ void cp_wait0() {
    asm volatile("cp.async.wait_group 0;" ::: "memory");
}
__device__ __forceinline__ void ldmx4(uint32_t addr, uint32_t* r) {
    asm volatile("ldmatrix.sync.aligned.m8n8.x4.shared.b16 {%0,%1,%2,%3}, [%4];"
                 : "=r"(r[0]), "=r"(r[1]), "=r"(r[2]), "=r"(r[3]) : "r"(addr));
}
__device__ __forceinline__ void ldmx4t(uint32_t addr, uint32_t* r) {
    asm volatile("ldmatrix.sync.aligned.m8n8.x4.trans.shared.b16 {%0,%1,%2,%3}, [%4];"
                 : "=r"(r[0]), "=r"(r[1]), "=r"(r[2]), "=r"(r[3]) : "r"(addr));
}
__device__ __forceinline__ void mma_bf16(float* d, const uint32_t* a,
                                         uint32_t b0, uint32_t b1) {
    asm volatile(
        "mma.sync.aligned.m16n8k16.row.col.f32.bf16.bf16.f32 "
        "{%0,%1,%2,%3}, {%4,%5,%6,%7}, {%8,%9}, {%0,%1,%2,%3};"
        : "+f"(d[0]), "+f"(d[1]), "+f"(d[2]), "+f"(d[3])
        : "r"(a[0]), "r"(a[1]), "r"(a[2]), "r"(a[3]), "r"(b0), "r"(b1));
}

// ---------------------------------------------------------------------------
// Kernel 0: W [256,128] fp32 -> bf16 hi/lo image, [K][N] row-major, swizzled.
// byte offset = k*256 + ((n*2) ^ ((k&7)<<4))
// ---------------------------------------------------------------------------
__global__ void prep_w_kernel(const float* __restrict__ W) {
    int idx = blockIdx.x * 256 + threadIdx.x;    // 0..32767
    int k = idx >> 7;
    int n = idx & 127;
    float w = W[idx];
    __nv_bfloat16 hi = __float2bfloat16(w);
    __nv_bfloat16 lo = __float2bfloat16(w - __bfloat162float(hi));
    uint32_t off = (uint32_t)k * 256 + (((uint32_t)n * 2) ^ ((k & 7) << 4));
    g_wh[off >> 1] = hi;
    g_wl[off >> 1] = lo;
}

// ---------------------------------------------------------------------------
// Kernel 1: h = A @ W + b via mma.sync bf16, 3-term split, fused col stats.
// 256 threads = 8 warps (4x2 over 128x128). 4 K-chunks, double buffered.
// ---------------------------------------------------------------------------
__global__ void __launch_bounds__(256, 1)
gemm_mma_kernel(const float* __restrict__ A, const float* __restrict__ bias)
{
    extern __shared__ char smem[];
    const uint32_t sm = smem_u32(smem);
    const int tid  = threadIdx.x;
    const int wid  = tid >> 5;
    const int lane = tid & 31;
    const int row0 = blockIdx.x * TM;
    const int warp_m = wid >> 1;          // 0..3 -> 32-row band
    const int warp_n = wid & 1;           // 0..1 -> 64-col band

    float* sbias = (float*)(smem + OFF_BIAS);
    if (tid < 128) sbias[tid] = bias[tid];

    // ---- producer setup: thread -> (row, k-half) ----
    const int pr = tid >> 1;
    const int ph = tid & 1;
    const bool pvalid = (row0 + pr) < U_NODES;
    const float* aptr = A + (size_t)(row0 + pr) * F_DIM + ph * 32;
    uint32_t a_sts[4];
#pragma unroll
    for (int i = 0; i < 4; i++)
        a_sts[i] = (uint32_t)pr * 128 + (((uint32_t)(ph * 64 + i * 16)) ^ ((pr & 7) << 4));

    float fA[32];
    auto lda = [&](int c) {
        if (pvalid) {
            const float4* p = (const float4*)(aptr + c * KC);
#pragma unroll
            for (int i = 0; i < 8; i++) {
                float4 v = p[i];
                fA[i * 4 + 0] = v.x; fA[i * 4 + 1] = v.y;
                fA[i * 4 + 2] = v.z; fA[i * 4 + 3] = v.w;
            }
        } else {
#pragma unroll
            for (int i = 0; i < 32; i++) fA[i] = 0.f;
        }
    };
    auto stsA = [&](int stage) {
        uint32_t hw[16], lw[16];
#pragma unroll
        for (int p = 0; p < 16; p++) {
            float x0 = fA[2 * p], x1 = fA[2 * p + 1];
            __nv_bfloat16 h0 = __float2bfloat16(x0);
            __nv_bfloat16 h1 = __float2bfloat16(x1);
            __nv_bfloat16 l0 = __float2bfloat16(x0 - __bfloat162float(h0));
            __nv_bfloat16 l1 = __float2bfloat16(x1 - __bfloat162float(h1));
            hw[p] = packbf(h0, h1);
            lw[p] = packbf(l0, l1);
        }
        const uint32_t ah = sm + OFF_A + stage * 32768;
        const uint32_t al = ah + 16384;
#pragma unroll
        for (int i = 0; i < 4; i++) {
            sts128(ah + a_sts[i], hw[4 * i], hw[4 * i + 1], hw[4 * i + 2], hw[4 * i + 3]);
            sts128(al + a_sts[i], lw[4 * i], lw[4 * i + 1], lw[4 * i + 2], lw[4 * i + 3]);
        }
    };
    auto ldw = [&](int c, int stage) {
        const uint32_t wh = sm + OFF_W + stage * 32768;
        const uint32_t wl = wh + 16384;
#pragma unroll
        for (int j = 0; j < 4; j++) {
            int idx = tid + j * 256;                 // 16B unit index (0..1023)
            cp16(wh + idx * 16, (const char*)g_wh + (size_t)c * 16384 + idx * 16);
            cp16(wl + idx * 16, (const char*)g_wl + (size_t)c * 16384 + idx * 16);
        }
    };

    // ---- MMA-side precomputed addressing ----
    uint32_t aoff[2], axor[2];
#pragma unroll
    for (int am = 0; am < 2; am++) {
        int r = warp_m * 32 + am * 16 + (lane & 15);
        aoff[am] = (uint32_t)r * 128;
        axor[am] = (uint32_t)(r & 7) << 4;
    }
    const uint32_t acolb = (uint32_t)(lane >> 4) * 16;
    const int bk = lane & 15;
    uint32_t bcol[4];
#pragma unroll
    for (int nb = 0; nb < 4; nb++)
        bcol[nb] = (((uint32_t)(warp_n * 64 + nb * 16 + (lane >> 4) * 8) * 2)
                    ^ ((bk & 7) << 4));
    const uint32_t brow = (uint32_t)bk * 256;

    float acc[2][8][4];
#pragma unroll
    for (int am = 0; am < 2; am++)
#pragma unroll
        for (int na = 0; na < 8; na++)
#pragma unroll
            for (int q = 0; q < 4; q++) acc[am][na][q] = 0.f;

    // ---- prologue: chunk 0 ----
    lda(0);
    stsA(0);
    ldw(0, 0);
    cp_commit();

    for (int c = 0; c < NCH; c++) {
        const int stage = c & 1;
        if (c + 1 < NCH) lda(c + 1);
        cp_wait0();
        __syncthreads();

        const uint32_t Ahb = sm + OFF_A + stage * 32768;
        const uint32_t Whb = sm + OFF_W + stage * 32768;
#pragma unroll
        for (int term = 0; term < 3; term++) {
            const uint32_t Ab = Ahb + ((term == 1) ? 16384 : 0);
            const uint32_t Bb = Whb + ((term == 2) ? 16384 : 0);
#pragma unroll
            for (int ks = 0; ks < 4; ks++) {
                uint32_t af[2][4];
#pragma unroll
                for (int am = 0; am < 2; am++)
                    ldmx4(Ab + aoff[am] + ((acolb + ks * 32) ^ axor[am]), af[am]);
                uint32_t bf[4][4];
#pragma unroll
                for (int nb = 0; nb < 4; nb++)
                    ldmx4t(Bb + (uint32_t)ks * 16 * 256 + brow + bcol[nb], bf[nb]);
#pragma unroll
                for (int am = 0; am < 2; am++)
#pragma unroll
                    for (int na = 0; na < 8; na++)
                        mma_bf16(acc[am][na], af[am],
                                 bf[na >> 1][(na & 1) * 2],
                                 bf[na >> 1][(na & 1) * 2 + 1]);
            }
        }

        if (c + 1 < NCH) {
            stsA(stage ^ 1);
            ldw(c + 1, stage ^ 1);
            cp_commit();
        }
    }

    // ---- epilogue ----
    __syncthreads();                       // all mma reads done before reuse
    float* ht = (float*)(smem + OFF_A);    // [128][129] fp32 tile (66KB)
#pragma unroll
    for (int am = 0; am < 2; am++) {
        const int r0 = warp_m * 32 + am * 16 + (lane >> 2);
#pragma unroll
        for (int na = 0; na < 8; na++) {
            const int col = warp_n * 64 + na * 8 + (lane & 3) * 2;
            ht[r0 * 129 + col]           = acc[am][na][0];
            ht[r0 * 129 + col + 1]       = acc[am][na][1];
            ht[(r0 + 8) * 129 + col]     = acc[am][na][2];
            ht[(r0 + 8) * 129 + col + 1] = acc[am][na][3];
        }
    }
    __syncthreads();

    const int validRows = (U_NODES - row0 < TM) ? (U_NODES - row0) : TM;

    // store h (+bias), two threads per row
    {
        const int r = tid >> 1;
        const int half = tid & 1;
        if (r < validRows) {
            float* dst = g_h + (size_t)(row0 + r) * E_DIM + half * 64;
            const float* src = ht + r * 129 + half * 64;
            const float* bb  = sbias + half * 64;
#pragma unroll
            for (int j = 0; j < 16; j++) {
                float4 v = make_float4(src[4 * j] + bb[4 * j],
                                       src[4 * j + 1] + bb[4 * j + 1],
                                       src[4 * j + 2] + bb[4 * j + 2],
                                       src[4 * j + 3] + bb[4 * j + 3]);
                *(float4*)(dst + 4 * j) = v;
            }
        }
    }

    // column stats (deterministic, per-CTA)
    if (tid < 128) {
        const int e = tid;
        const float be = sbias[e];
        float s = 0.f, q = 0.f;
        for (int r = 0; r < validRows; r++) {
            float x = ht[r * 129 + e] + be;
            s += x; q += x * x;
        }
        g_part[blockIdx.x * 256 + e]       = s;
        g_part[blockIdx.x * 256 + 128 + e] = q;
    }
}

// ---------------------------------------------------------------------------
// Kernel 2: finalize BN stats (one block per embedding column)
// ---------------------------------------------------------------------------
__global__ void finalize_stats_kernel(const float* __restrict__ gamma,
                                      const float* __restrict__ beta)
{
    __shared__ float ss[256], sq[256];
    const int e = blockIdx.x;
    const int t = threadIdx.x;
    float s = 0.f, q = 0.f;
    for (int i = t; i < NTILES; i += 256) {
        s += g_part[i * 256 + e];
        q += g_part[i * 256 + 128 + e];
    }
    ss[t] = s; sq[t] = q;
    __syncthreads();
    for (int st = 128; st > 0; st >>= 1) {
        if (t < st) { ss[t] += ss[t + st]; sq[t] += sq[t + st]; }
        __syncthreads();
    }
    if (t == 0) {
        const float mu  = ss[0] * (1.0f / U_NODES);
        const float var = sq[0] * (1.0f / U_NODES) - mu * mu;
        const float a   = gamma[e] * rsqrtf(var + BN_EPS);
        g_ab[e]         = a;
        g_ab[E_DIM + e] = beta[e] - mu * a;
    }
}

// ---------------------------------------------------------------------------
// Kernel 3: out[b] = mean_k tanh(a * h[idx[b,k]] + c)
// ---------------------------------------------------------------------------
__global__ void __launch_bounds__(128)
gather_mean_kernel(const int* __restrict__ idx, float* __restrict__ out)
{
    __shared__ int sidx[K_SAMP];
    const int b = blockIdx.x;
    const int e = threadIdx.x;
    if (e < K_SAMP) sidx[e] = idx[b * K_SAMP + e];
    __syncthreads();

    const float a = g_ab[e];
    const float c = g_ab[E_DIM + e];
    float accv = 0.f;
#pragma unroll
    for (int k = 0; k < K_SAMP; k++) {
        const float v = __ldg(g_h + (size_t)sidx[k] * E_DIM + e);
        float x = a * v + c;
        x = fminf(fmaxf(x, -15.f), 15.f);
        const float ex = __expf(2.f * x);
        accv += 1.f - __fdividef(2.f, ex + 1.f);
    }
    out[(size_t)b * E_DIM + e] = accv * (1.0f / K_SAMP);
}

// ---------------------------------------------------------------------------
extern "C" void kernel_launch(void* const* d_in, const int* in_sizes, int n_in,
                              void* d_out, int out_size)
{
    const float* features = (const float*)d_in[0];
    const float* W        = (const float*)d_in[1];
    const float* bias     = (const float*)d_in[2];
    const float* gamma    = (const float*)d_in[3];
    const float* beta     = (const float*)d_in[4];
    const int*   sidx     = (const int*)d_in[5];
    float*       out      = (float*)d_out;

    cudaFuncSetAttribute(gemm_mma_kernel,
                         cudaFuncAttributeMaxDynamicSharedMemorySize, SMEM_TOTAL);

    prep_w_kernel<<<128, 256>>>(W);
    gemm_mma_kernel<<<NTILES, 256, SMEM_TOTAL>>>(features, bias);
    finalize_stats_kernel<<<128, 256>>>(gamma, beta);
    gather_mean_kernel<<<B_ROWS, E_DIM>>>(sidx, out);
}

// round 4
// speedup vs baseline: 2.1346x; 1.1350x over previous
#include <cuda_runtime.h>
#include <cuda_bf16.h>
#include <cstdint>

// ---------------------------------------------------------------------------
// Problem constants
// ---------------------------------------------------------------------------
#define U_NODES 200000
#define F_DIM   256
#define E_DIM   128
#define B_ROWS  20000
#define K_SAMP  33
#define BN_EPS  1e-5f

#define TM      128
#define KC      64                        // K chunk (bf16 elems)
#define NCH     (F_DIM / KC)              // 4
#define NTILES  ((U_NODES + TM - 1) / TM) // 1563

// SMEM layout (bytes, dynamic)
#define OFF_BIAS   0
#define OFF_W      1024                       // W hi 64KB, W lo 64KB (whole K)
#define OFF_A      (OFF_W + 131072)           // 2 stages x (hi 16K + lo 16K)
#define SMEM_TOTAL (OFF_A + 65536)            // 197632

// ---------------------------------------------------------------------------
// Device scratch
// ---------------------------------------------------------------------------
__device__ float g_h[(size_t)U_NODES * E_DIM];
__device__ float g_part[NTILES * 2 * E_DIM];
__device__ float g_ab[2 * E_DIM];
// W images: [K=256][N=128] bf16 row-major, 16B-column XOR-swizzled by (k&7)
__device__ __align__(16) __nv_bfloat16 g_wh[F_DIM * E_DIM];
__device__ __align__(16) __nv_bfloat16 g_wl[F_DIM * E_DIM];

// ---------------------------------------------------------------------------
// Helpers
// ---------------------------------------------------------------------------
__device__ __forceinline__ uint32_t smem_u32(const void* p) {
    uint32_t a;
    asm("{ .reg .u64 t; cvta.to.shared.u64 t, %1; cvt.u32.u64 %0, t; }"
        : "=r"(a) : "l"(p));
    return a;
}
__device__ __forceinline__ uint32_t packbf(__nv_bfloat16 a, __nv_bfloat16 b) {
    return ((uint32_t)__bfloat16_as_ushort(b) << 16) | __bfloat16_as_ushort(a);
}
__device__ __forceinline__ void sts128(uint32_t addr, uint32_t a, uint32_t b,
                                       uint32_t c, uint32_t d) {
    asm volatile("st.shared.v4.b32 [%0], {%1, %2, %3, %4};"
                 :: "r"(addr), "r"(a), "r"(b), "r"(c), "r"(d) : "memory");
}
__device__ __forceinline__ void cp16(uint32_t s, const void* g) {
    asm volatile("cp.async.cg.shared.global [%0], [%1], 16;"
                 :: "r"(s), "l"(g) : "memory");
}
__device__ __forceinline__ void cp_commit() {
    asm volatile("cp.async.commit_group;" ::: "memory");
}
__device__ __forceinline__ void cp_wait0() {
    asm volatile("cp.async.wait_group 0;" ::: "memory");
}
__device__ __forceinline__ void ldmx4(uint32_t addr, uint32_t* r) {
    asm volatile("ldmatrix.sync.aligned.m8n8.x4.shared.b16 {%0,%1,%2,%3}, [%4];"
                 : "=r"(r[0]), "=r"(r[1]), "=r"(r[2]), "=r"(r[3]) : "r"(addr));
}
__device__ __forceinline__ void ldmx4t(uint32_t addr, uint32_t* r) {
    asm volatile("ldmatrix.sync.aligned.m8n8.x4.trans.shared.b16 {%0,%1,%2,%3}, [%4];"
                 : "=r"(r[0]), "=r"(r[1]), "=r"(r[2]), "=r"(r[3]) : "r"(addr));
}
__device__ __forceinline__ void mma_bf16(float* d, const uint32_t* a,
                                         uint32_t b0, uint32_t b1) {
    asm volatile(
        "mma.sync.aligned.m16n8k16.row.col.f32.bf16.bf16.f32 "
        "{%0,%1,%2,%3}, {%4,%5,%6,%7}, {%8,%9}, {%0,%1,%2,%3};"
        : "+f"(d[0]), "+f"(d[1]), "+f"(d[2]), "+f"(d[3])
        : "r"(a[0]), "r"(a[1]), "r"(a[2]), "r"(a[3]), "r"(b0), "r"(b1));
}

// ---------------------------------------------------------------------------
// Kernel 0: W [256,128] fp32 -> bf16 hi/lo image, [K][N] row-major, swizzled.
// byte offset = k*256 + ((n*2) ^ ((k&7)<<4))
// ---------------------------------------------------------------------------
__global__ void prep_w_kernel(const float* __restrict__ W) {
    int idx = blockIdx.x * 256 + threadIdx.x;    // 0..32767
    int k = idx >> 7;
    int n = idx & 127;
    float w = W[idx];
    __nv_bfloat16 hi = __float2bfloat16(w);
    __nv_bfloat16 lo = __float2bfloat16(w - __bfloat162float(hi));
    uint32_t off = (uint32_t)k * 256 + (((uint32_t)n * 2) ^ ((k & 7) << 4));
    g_wh[off >> 1] = hi;
    g_wl[off >> 1] = lo;
}

// ---------------------------------------------------------------------------
// Kernel 1: h = A @ W + b via mma.sync bf16, 3-term split, fused col stats.
// W fully resident in SMEM (loaded once). A software-pipelined:
// at chunk c: STS chunk c+1 (regs loaded at c-1), LDG chunk c+2, MMA chunk c.
// ---------------------------------------------------------------------------
__global__ void __launch_bounds__(256, 1)
gemm_mma_kernel(const float* __restrict__ A, const float* __restrict__ bias)
{
    extern __shared__ char smem[];
    const uint32_t sm = smem_u32(smem);
    const int tid  = threadIdx.x;
    const int wid  = tid >> 5;
    const int lane = tid & 31;
    const int row0 = blockIdx.x * TM;
    const int warp_m = wid >> 1;          // 0..3 -> 32-row band
    const int warp_n = wid & 1;           // 0..1 -> 64-col band

    float* sbias = (float*)(smem + OFF_BIAS);
    if (tid < 128) sbias[tid] = bias[tid];

    // ---- load full W (hi+lo, 128KB) once via cp.async ----
    {
        const char* srcH = (const char*)g_wh;
        const char* srcL = (const char*)g_wl;
        const uint32_t dH = sm + OFF_W;
        const uint32_t dL = sm + OFF_W + 65536;
#pragma unroll
        for (int j = 0; j < 16; j++) {
            const int u = tid + j * 256;          // 16B units, 0..4095
            cp16(dH + u * 16, srcH + (size_t)u * 16);
            cp16(dL + u * 16, srcL + (size_t)u * 16);
        }
        cp_commit();
    }

    // ---- producer setup: thread -> (row, k-half) ----
    const int pr = tid >> 1;
    const int ph = tid & 1;
    const bool pvalid = (row0 + pr) < U_NODES;
    const float* aptr = A + (size_t)(row0 + pr) * F_DIM + ph * 32;
    uint32_t a_sts[4];
#pragma unroll
    for (int i = 0; i < 4; i++)
        a_sts[i] = (uint32_t)pr * 128 + (((uint32_t)(ph * 64 + i * 16)) ^ ((pr & 7) << 4));

    float fA[32];
    auto lda = [&](int c) {
        if (pvalid) {
            const float4* p = (const float4*)(aptr + c * KC);
#pragma unroll
            for (int i = 0; i < 8; i++) {
                float4 v = p[i];
                fA[i * 4 + 0] = v.x; fA[i * 4 + 1] = v.y;
                fA[i * 4 + 2] = v.z; fA[i * 4 + 3] = v.w;
            }
        } else {
#pragma unroll
            for (int i = 0; i < 32; i++) fA[i] = 0.f;
        }
    };
    auto stsA = [&](int stage) {
        uint32_t hw[16], lw[16];
#pragma unroll
        for (int p = 0; p < 16; p++) {
            float x0 = fA[2 * p], x1 = fA[2 * p + 1];
            __nv_bfloat16 h0 = __float2bfloat16(x0);
            __nv_bfloat16 h1 = __float2bfloat16(x1);
            __nv_bfloat16 l0 = __float2bfloat16(x0 - __bfloat162float(h0));
            __nv_bfloat16 l1 = __float2bfloat16(x1 - __bfloat162float(h1));
            hw[p] = packbf(h0, h1);
            lw[p] = packbf(l0, l1);
        }
        const uint32_t ah = sm + OFF_A + stage * 32768;
        const uint32_t al = ah + 16384;
#pragma unroll
        for (int i = 0; i < 4; i++) {
            sts128(ah + a_sts[i], hw[4 * i], hw[4 * i + 1], hw[4 * i + 2], hw[4 * i + 3]);
            sts128(al + a_sts[i], lw[4 * i], lw[4 * i + 1], lw[4 * i + 2], lw[4 * i + 3]);
        }
    };

    // ---- MMA-side precomputed addressing ----
    uint32_t aoff[2], axor[2];
#pragma unroll
    for (int am = 0; am < 2; am++) {
        int r = warp_m * 32 + am * 16 + (lane & 15);
        aoff[am] = (uint32_t)r * 128;
        axor[am] = (uint32_t)(r & 7) << 4;
    }
    const uint32_t acolb = (uint32_t)(lane >> 4) * 16;
    const int bk = lane & 15;
    uint32_t bcol[4];
#pragma unroll
    for (int nb = 0; nb < 4; nb++)
        bcol[nb] = (((uint32_t)(warp_n * 64 + nb * 16 + (lane >> 4) * 8) * 2)
                    ^ ((bk & 7) << 4));
    const uint32_t brow = (uint32_t)bk * 256;

    float acc[2][8][4];
#pragma unroll
    for (int am = 0; am < 2; am++)
#pragma unroll
        for (int na = 0; na < 8; na++)
#pragma unroll
            for (int q = 0; q < 4; q++) acc[am][na][q] = 0.f;

    // ---- prologue ----
    lda(0);
    stsA(0);
    lda(1);
    cp_wait0();              // W resident
    __syncthreads();

    for (int c = 0; c < NCH; c++) {
        const int stage = c & 1;
        if (c + 1 < NCH) stsA(stage ^ 1);    // convert+store chunk c+1
        if (c + 2 < NCH) lda(c + 2);         // issue LDGs for chunk c+2

        const uint32_t Ahb = sm + OFF_A + stage * 32768;
        const uint32_t Alb = Ahb + 16384;
        const uint32_t Whb = sm + OFF_W + (uint32_t)c * 16384;
        const uint32_t Wlb = Whb + 65536;

#pragma unroll
        for (int ks = 0; ks < 4; ks++) {
            uint32_t ah[2][4], al[2][4];
#pragma unroll
            for (int am = 0; am < 2; am++) {
                const uint32_t ao = aoff[am] + ((acolb + ks * 32) ^ axor[am]);
                ldmx4(Ahb + ao, ah[am]);
                ldmx4(Alb + ao, al[am]);
            }
            uint32_t bh[4][4], bl[4][4];
#pragma unroll
            for (int nb = 0; nb < 4; nb++) {
                const uint32_t bo = (uint32_t)ks * 4096 + brow + bcol[nb];
                ldmx4t(Whb + bo, bh[nb]);
                ldmx4t(Wlb + bo, bl[nb]);
            }
#pragma unroll
            for (int am = 0; am < 2; am++)
#pragma unroll
                for (int na = 0; na < 8; na++) {
                    const uint32_t b0 = bh[na >> 1][(na & 1) * 2];
                    const uint32_t b1 = bh[na >> 1][(na & 1) * 2 + 1];
                    mma_bf16(acc[am][na], ah[am], b0, b1);
                    mma_bf16(acc[am][na], al[am], b0, b1);
                    mma_bf16(acc[am][na], ah[am],
                             bl[na >> 1][(na & 1) * 2],
                             bl[na >> 1][(na & 1) * 2 + 1]);
                }
        }
        __syncthreads();
    }

    // ---- epilogue: stage acc to smem (reuse W area), store h + stats ----
    float* ht = (float*)(smem + OFF_W);    // [128][129] fp32 (66KB)
#pragma unroll
    for (int am = 0; am < 2; am++) {
        const int r0 = warp_m * 32 + am * 16 + (lane >> 2);
#pragma unroll
        for (int na = 0; na < 8; na++) {
            const int col = warp_n * 64 + na * 8 + (lane & 3) * 2;
            ht[r0 * 129 + col]           = acc[am][na][0];
            ht[r0 * 129 + col + 1]       = acc[am][na][1];
            ht[(r0 + 8) * 129 + col]     = acc[am][na][2];
            ht[(r0 + 8) * 129 + col + 1] = acc[am][na][3];
        }
    }
    __syncthreads();

    const int validRows = (U_NODES - row0 < TM) ? (U_NODES - row0) : TM;

    // store h (+bias), two threads per row
    {
        const int r = tid >> 1;
        const int half = tid & 1;
        if (r < validRows) {
            float* dst = g_h + (size_t)(row0 + r) * E_DIM + half * 64;
            const float* src = ht + r * 129 + half * 64;
            const float* bb  = sbias + half * 64;
#pragma unroll
            for (int j = 0; j < 16; j++) {
                float4 v = make_float4(src[4 * j] + bb[4 * j],
                                       src[4 * j + 1] + bb[4 * j + 1],
                                       src[4 * j + 2] + bb[4 * j + 2],
                                       src[4 * j + 3] + bb[4 * j + 3]);
                *(float4*)(dst + 4 * j) = v;
            }
        }
    }

    // column stats (deterministic, per-CTA)
    if (tid < 128) {
        const int e = tid;
        const float be = sbias[e];
        float s = 0.f, q = 0.f;
        for (int r = 0; r < validRows; r++) {
            float x = ht[r * 129 + e] + be;
            s += x; q += x * x;
        }
        g_part[blockIdx.x * 256 + e]       = s;
        g_part[blockIdx.x * 256 + 128 + e] = q;
    }
}

// ---------------------------------------------------------------------------
// Kernel 2: finalize BN stats (one block per embedding column)
// ---------------------------------------------------------------------------
__global__ void finalize_stats_kernel(const float* __restrict__ gamma,
                                      const float* __restrict__ beta)
{
    __shared__ float ss[256], sq[256];
    const int e = blockIdx.x;
    const int t = threadIdx.x;
    float s = 0.f, q = 0.f;
    for (int i = t; i < NTILES; i += 256) {
        s += g_part[i * 256 + e];
        q += g_part[i * 256 + 128 + e];
    }
    ss[t] = s; sq[t] = q;
    __syncthreads();
    for (int st = 128; st > 0; st >>= 1) {
        if (t < st) { ss[t] += ss[t + st]; sq[t] += sq[t + st]; }
        __syncthreads();
    }
    if (t == 0) {
        const float mu  = ss[0] * (1.0f / U_NODES);
        const float var = sq[0] * (1.0f / U_NODES) - mu * mu;
        const float a   = gamma[e] * rsqrtf(var + BN_EPS);
        g_ab[e]         = a;
        g_ab[E_DIM + e] = beta[e] - mu * a;
    }
}

// ---------------------------------------------------------------------------
// Kernel 3: out[b] = mean_k tanh(a * h[idx[b,k]] + c)   (tanh.approx.f32)
// ---------------------------------------------------------------------------
__global__ void __launch_bounds__(128)
gather_mean_kernel(const int* __restrict__ idx, float* __restrict__ out)
{
    __shared__ int sidx[K_SAMP];
    const int b = blockIdx.x;
    const int e = threadIdx.x;
    if (e < K_SAMP) sidx[e] = idx[b * K_SAMP + e];
    __syncthreads();

    const float a = g_ab[e];
    const float c = g_ab[E_DIM + e];
    float accv = 0.f;
#pragma unroll
    for (int k = 0; k < K_SAMP; k++) {
        const float v = __ldg(g_h + (size_t)sidx[k] * E_DIM + e);
        float t;
        asm("tanh.approx.f32 %0, %1;" : "=f"(t) : "f"(fmaf(a, v, c)));
        accv += t;
    }
    out[(size_t)b * E_DIM + e] = accv * (1.0f / K_SAMP);
}

// ---------------------------------------------------------------------------
extern "C" void kernel_launch(void* const* d_in, const int* in_sizes, int n_in,
                              void* d_out, int out_size)
{
    const float* features = (const float*)d_in[0];
    const float* W        = (const float*)d_in[1];
    const float* bias     = (const float*)d_in[2];
    const float* gamma    = (const float*)d_in[3];
    const float* beta     = (const float*)d_in[4];
    const int*   sidx     = (const int*)d_in[5];
    float*       out      = (float*)d_out;

    cudaFuncSetAttribute(gemm_mma_kernel,
                         cudaFuncAttributeMaxDynamicSharedMemorySize, SMEM_TOTAL);

    prep_w_kernel<<<128, 256>>>(W);
    gemm_mma_kernel<<<NTILES, 256, SMEM_TOTAL>>>(features, bias);
    finalize_stats_kernel<<<128, 256>>>(gamma, beta);
    gather_mean_kernel<<<B_ROWS, E_DIM>>>(sidx, out);
}

// round 5
// speedup vs baseline: 2.1595x; 1.0116x over previous
#include <cuda_runtime.h>
#include <cuda_bf16.h>
#include <cstdint>

// ---------------------------------------------------------------------------
// Problem constants
// ---------------------------------------------------------------------------
#define U_NODES 200000
#define F_DIM   256
#define E_DIM   128
#define B_ROWS  20000
#define K_SAMP  33
#define BN_EPS  1e-5f

#define TM      128
#define KC      64                        // K chunk (bf16 elems)
#define NCH     (F_DIM / KC)              // 4
#define NTILES  ((U_NODES + TM - 1) / TM) // 1563

// SMEM layout (bytes, dynamic)
#define OFF_BIAS   0
#define OFF_W      1024                       // W hi 64KB, W lo 64KB (whole K)
#define OFF_A      (OFF_W + 131072)           // 2 stages x (hi 16K + lo 16K)
#define SMEM_TOTAL (OFF_A + 65536)            // 197632

// ---------------------------------------------------------------------------
// Device scratch
// ---------------------------------------------------------------------------
__device__ float g_h[(size_t)U_NODES * E_DIM];
__device__ float g_part[NTILES * 2 * E_DIM];
__device__ float g_ab[2 * E_DIM];
// W images: [K=256][N=128] bf16 row-major, 16B-column XOR-swizzled by (k&7)
__device__ __align__(16) __nv_bfloat16 g_wh[F_DIM * E_DIM];
__device__ __align__(16) __nv_bfloat16 g_wl[F_DIM * E_DIM];

// ---------------------------------------------------------------------------
// Helpers
// ---------------------------------------------------------------------------
__device__ __forceinline__ uint32_t smem_u32(const void* p) {
    uint32_t a;
    asm("{ .reg .u64 t; cvta.to.shared.u64 t, %1; cvt.u32.u64 %0, t; }"
        : "=r"(a) : "l"(p));
    return a;
}
__device__ __forceinline__ void sts128(uint32_t addr, uint32_t a, uint32_t b,
                                       uint32_t c, uint32_t d) {
    asm volatile("st.shared.v4.b32 [%0], {%1, %2, %3, %4};"
                 :: "r"(addr), "r"(a), "r"(b), "r"(c), "r"(d) : "memory");
}
__device__ __forceinline__ void cp16(uint32_t s, const void* g) {
    asm volatile("cp.async.cg.shared.global [%0], [%1], 16;"
                 :: "r"(s), "l"(g) : "memory");
}
__device__ __forceinline__ void cp_commit() {
    asm volatile("cp.async.commit_group;" ::: "memory");
}
__device__ __forceinline__ void cp_wait0() {
    asm volatile("cp.async.wait_group 0;" ::: "memory");
}
__device__ __forceinline__ void ldmx4(uint32_t addr, uint32_t* r) {
    asm volatile("ldmatrix.sync.aligned.m8n8.x4.shared.b16 {%0,%1,%2,%3}, [%4];"
                 : "=r"(r[0]), "=r"(r[1]), "=r"(r[2]), "=r"(r[3]) : "r"(addr));
}
__device__ __forceinline__ void ldmx4t(uint32_t addr, uint32_t* r) {
    asm volatile("ldmatrix.sync.aligned.m8n8.x4.trans.shared.b16 {%0,%1,%2,%3}, [%4];"
                 : "=r"(r[0]), "=r"(r[1]), "=r"(r[2]), "=r"(r[3]) : "r"(addr));
}
__device__ __forceinline__ void mma_bf16(float* d, const uint32_t* a,
                                         uint32_t b0, uint32_t b1) {
    asm volatile(
        "mma.sync.aligned.m16n8k16.row.col.f32.bf16.bf16.f32 "
        "{%0,%1,%2,%3}, {%4,%5,%6,%7}, {%8,%9}, {%0,%1,%2,%3};"
        : "+f"(d[0]), "+f"(d[1]), "+f"(d[2]), "+f"(d[3])
        : "r"(a[0]), "r"(a[1]), "r"(a[2]), "r"(a[3]), "r"(b0), "r"(b1));
}
// truncation split of a pair of fp32 into hi-bf16x2 and lo-bf16x2
__device__ __forceinline__ void split_pair(float x0, float x1,
                                           uint32_t& hi, uint32_t& lo) {
    const uint32_t u0 = __float_as_uint(x0);
    const uint32_t u1 = __float_as_uint(x1);
    hi = __byte_perm(u0, u1, 0x7632);                 // [x1.hi16 : x0.hi16]
    const float h0 = __uint_as_float(u0 & 0xFFFF0000u);
    const float h1 = __uint_as_float(u1 & 0xFFFF0000u);
    const float l0 = x0 - h0;                         // exact
    const float l1 = x1 - h1;                         // exact
    asm("cvt.rn.bf16x2.f32 %0, %1, %2;" : "=r"(lo) : "f"(l1), "f"(l0));
}

// ---------------------------------------------------------------------------
// Kernel 0: W [256,128] fp32 -> bf16 hi/lo image, [K][N] row-major, swizzled.
// hi by truncation (exact residual), lo = RN(x - hi).
// byte offset = k*256 + ((n*2) ^ ((k&7)<<4))
// ---------------------------------------------------------------------------
__global__ void prep_w_kernel(const float* __restrict__ W) {
    int idx = blockIdx.x * 256 + threadIdx.x;    // 0..32767
    int k = idx >> 7;
    int n = idx & 127;
    float w = W[idx];
    uint32_t u = __float_as_uint(w);
    float hf = __uint_as_float(u & 0xFFFF0000u);
    __nv_bfloat16 hi = __ushort_as_bfloat16((unsigned short)(u >> 16));
    __nv_bfloat16 lo = __float2bfloat16(w - hf);
    uint32_t off = (uint32_t)k * 256 + (((uint32_t)n * 2) ^ ((k & 7) << 4));
    g_wh[off >> 1] = hi;
    g_wl[off >> 1] = lo;
}

// ---------------------------------------------------------------------------
// Kernel 1: h = A @ W + b via mma.sync bf16, 3-term split, fused col stats.
// 512 threads = 16 warps (4x4 grid of 32x32 warp tiles), W resident in SMEM,
// A software-pipelined (STS c+1, LDG c+2, MMA c).
// ---------------------------------------------------------------------------
__global__ void __launch_bounds__(512, 1)
gemm_mma_kernel(const float* __restrict__ A, const float* __restrict__ bias)
{
    extern __shared__ char smem[];
    const uint32_t sm = smem_u32(smem);
    const int tid  = threadIdx.x;
    const int wid  = tid >> 5;
    const int lane = tid & 31;
    const int row0 = blockIdx.x * TM;
    const int warp_m = wid >> 2;          // 0..3 -> 32-row band
    const int warp_n = wid & 3;           // 0..3 -> 32-col band

    float* sbias = (float*)(smem + OFF_BIAS);
    if (tid < 128) sbias[tid] = bias[tid];

    // ---- load full W (hi+lo, 128KB) once via cp.async ----
    {
        const char* srcH = (const char*)g_wh;
        const char* srcL = (const char*)g_wl;
        const uint32_t dH = sm + OFF_W;
        const uint32_t dL = sm + OFF_W + 65536;
#pragma unroll
        for (int j = 0; j < 8; j++) {
            const int u = tid + j * 512;          // 16B units, 0..4095
            cp16(dH + u * 16, srcH + (size_t)u * 16);
            cp16(dL + u * 16, srcL + (size_t)u * 16);
        }
        cp_commit();
    }

    // ---- producer setup: thread -> (row, 16-float quarter) ----
    const int pr = tid >> 2;             // 0..127
    const int pq = tid & 3;              // quarter within 64-col chunk
    const bool pvalid = (row0 + pr) < U_NODES;
    const float* aptr = A + (size_t)(row0 + pr) * F_DIM + pq * 16;
    uint32_t a_sts[2];
#pragma unroll
    for (int i = 0; i < 2; i++)
        a_sts[i] = (uint32_t)pr * 128 +
                   (((uint32_t)(pq * 32 + i * 16)) ^ ((pr & 7) << 4));

    float fA[16];
    auto lda = [&](int c) {
        if (pvalid) {
            const float4* p = (const float4*)(aptr + c * KC);
#pragma unroll
            for (int i = 0; i < 4; i++) {
                float4 v = p[i];
                fA[i * 4 + 0] = v.x; fA[i * 4 + 1] = v.y;
                fA[i * 4 + 2] = v.z; fA[i * 4 + 3] = v.w;
            }
        } else {
#pragma unroll
            for (int i = 0; i < 16; i++) fA[i] = 0.f;
        }
    };
    auto stsA = [&](int stage) {
        uint32_t hw[8], lw[8];
#pragma unroll
        for (int p = 0; p < 8; p++)
            split_pair(fA[2 * p], fA[2 * p + 1], hw[p], lw[p]);
        const uint32_t ah = sm + OFF_A + stage * 32768;
        const uint32_t al = ah + 16384;
        sts128(ah + a_sts[0], hw[0], hw[1], hw[2], hw[3]);
        sts128(ah + a_sts[1], hw[4], hw[5], hw[6], hw[7]);
        sts128(al + a_sts[0], lw[0], lw[1], lw[2], lw[3]);
        sts128(al + a_sts[1], lw[4], lw[5], lw[6], lw[7]);
    };

    // ---- MMA-side precomputed addressing ----
    uint32_t aoff[2], axor[2];
#pragma unroll
    for (int am = 0; am < 2; am++) {
        int r = warp_m * 32 + am * 16 + (lane & 15);
        aoff[am] = (uint32_t)r * 128;
        axor[am] = (uint32_t)(r & 7) << 4;
    }
    const uint32_t acolb = (uint32_t)(lane >> 4) * 16;
    const int bk = lane & 15;
    uint32_t bcol[2];
#pragma unroll
    for (int nb = 0; nb < 2; nb++)
        bcol[nb] = (((uint32_t)(warp_n * 32 + nb * 16 + (lane >> 4) * 8) * 2)
                    ^ ((bk & 7) << 4));
    const uint32_t brow = (uint32_t)bk * 256;

    float acc[2][4][4];
#pragma unroll
    for (int am = 0; am < 2; am++)
#pragma unroll
        for (int na = 0; na < 4; na++)
#pragma unroll
            for (int q = 0; q < 4; q++) acc[am][na][q] = 0.f;

    // ---- prologue ----
    lda(0);
    stsA(0);
    lda(1);
    cp_wait0();              // W resident
    __syncthreads();

    for (int c = 0; c < NCH; c++) {
        const int stage = c & 1;
        if (c + 1 < NCH) stsA(stage ^ 1);    // convert+store chunk c+1
        if (c + 2 < NCH) lda(c + 2);         // issue LDGs for chunk c+2

        const uint32_t Ahb = sm + OFF_A + stage * 32768;
        const uint32_t Alb = Ahb + 16384;
        const uint32_t Whb = sm + OFF_W + (uint32_t)c * 16384;
        const uint32_t Wlb = Whb + 65536;

#pragma unroll
        for (int ks = 0; ks < 4; ks++) {
            uint32_t ah[2][4], al[2][4];
#pragma unroll
            for (int am = 0; am < 2; am++) {
                const uint32_t ao = aoff[am] + ((acolb + ks * 32) ^ axor[am]);
                ldmx4(Ahb + ao, ah[am]);
                ldmx4(Alb + ao, al[am]);
            }
#pragma unroll
            for (int nb = 0; nb < 2; nb++) {
                uint32_t bh[4], bl[4];
                const uint32_t bo = (uint32_t)ks * 4096 + brow + bcol[nb];
                ldmx4t(Whb + bo, bh);
                ldmx4t(Wlb + bo, bl);
#pragma unroll
                for (int am = 0; am < 2; am++)
#pragma unroll
                    for (int half = 0; half < 2; half++) {
                        float* d = acc[am][nb * 2 + half];
                        const uint32_t b0 = bh[half * 2];
                        const uint32_t b1 = bh[half * 2 + 1];
                        mma_bf16(d, ah[am], b0, b1);
                        mma_bf16(d, al[am], b0, b1);
                        mma_bf16(d, ah[am], bl[half * 2], bl[half * 2 + 1]);
                    }
            }
        }
        __syncthreads();
    }

    // ---- epilogue: stage acc to smem (reuse W area), store h + stats ----
    float* ht = (float*)(smem + OFF_W);    // [128][129] fp32 (66KB)
#pragma unroll
    for (int am = 0; am < 2; am++) {
        const int r0 = warp_m * 32 + am * 16 + (lane >> 2);
#pragma unroll
        for (int na = 0; na < 4; na++) {
            const int col = warp_n * 32 + na * 8 + (lane & 3) * 2;
            ht[r0 * 129 + col]           = acc[am][na][0];
            ht[r0 * 129 + col + 1]       = acc[am][na][1];
            ht[(r0 + 8) * 129 + col]     = acc[am][na][2];
            ht[(r0 + 8) * 129 + col + 1] = acc[am][na][3];
        }
    }
    __syncthreads();

    const int validRows = (U_NODES - row0 < TM) ? (U_NODES - row0) : TM;

    // store h (+bias): thread -> (row, 32-col quarter)
    {
        const int r = tid >> 2;
        const int q = tid & 3;
        if (r < validRows) {
            float* dst = g_h + (size_t)(row0 + r) * E_DIM + q * 32;
            const float* src = ht + r * 129 + q * 32;
            const float* bb  = sbias + q * 32;
#pragma unroll
            for (int j = 0; j < 8; j++) {
                float4 v = make_float4(src[4 * j] + bb[4 * j],
                                       src[4 * j + 1] + bb[4 * j + 1],
                                       src[4 * j + 2] + bb[4 * j + 2],
                                       src[4 * j + 3] + bb[4 * j + 3]);
                *(float4*)(dst + 4 * j) = v;
            }
        }
    }

    // column stats: 4 row-bands x 128 cols, then 4-way combine
    {
        float* red_s = (float*)(smem + OFF_A);          // 512 floats
        float* red_q = red_s + 512;
        const int e = tid & 127;
        const int band = tid >> 7;                      // 0..3
        const float be = sbias[e];
        float s = 0.f, q = 0.f;
        const int rEnd = min(band * 32 + 32, validRows);
        for (int r = band * 32; r < rEnd; r++) {
            float x = ht[r * 129 + e] + be;
            s += x; q += x * x;
        }
        red_s[band * 128 + e] = s;
        red_q[band * 128 + e] = q;
        __syncthreads();
        if (tid < 128) {
            float ts = red_s[tid] + red_s[128 + tid] +
                       red_s[256 + tid] + red_s[384 + tid];
            float tq = red_q[tid] + red_q[128 + tid] +
                       red_q[256 + tid] + red_q[384 + tid];
            g_part[blockIdx.x * 256 + tid]       = ts;
            g_part[blockIdx.x * 256 + 128 + tid] = tq;
        }
    }
}

// ---------------------------------------------------------------------------
// Kernel 2: finalize BN stats (one block per embedding column)
// ---------------------------------------------------------------------------
__global__ void finalize_stats_kernel(const float* __restrict__ gamma,
                                      const float* __restrict__ beta)
{
    __shared__ float ss[256], sq[256];
    const int e = blockIdx.x;
    const int t = threadIdx.x;
    float s = 0.f, q = 0.f;
    for (int i = t; i < NTILES; i += 256) {
        s += g_part[i * 256 + e];
        q += g_part[i * 256 + 128 + e];
    }
    ss[t] = s; sq[t] = q;
    __syncthreads();
    for (int st = 128; st > 0; st >>= 1) {
        if (t < st) { ss[t] += ss[t + st]; sq[t] += sq[t + st]; }
        __syncthreads();
    }
    if (t == 0) {
        const float mu  = ss[0] * (1.0f / U_NODES);
        const float var = sq[0] * (1.0f / U_NODES) - mu * mu;
        const float a   = gamma[e] * rsqrtf(var + BN_EPS);
        g_ab[e]         = a;
        g_ab[E_DIM + e] = beta[e] - mu * a;
    }
}

// ---------------------------------------------------------------------------
// Kernel 3: out[b] = mean_k tanh(a * h[idx[b,k]] + c)   (tanh.approx.f32)
// ---------------------------------------------------------------------------
__global__ void __launch_bounds__(128)
gather_mean_kernel(const int* __restrict__ idx, float* __restrict__ out)
{
    __shared__ int sidx[K_SAMP];
    const int b = blockIdx.x;
    const int e = threadIdx.x;
    if (e < K_SAMP) sidx[e] = idx[b * K_SAMP + e];
    __syncthreads();

    const float a = g_ab[e];
    const float c = g_ab[E_DIM + e];
    float accv = 0.f;
#pragma unroll
    for (int k = 0; k < K_SAMP; k++) {
        const float v = __ldg(g_h + (size_t)sidx[k] * E_DIM + e);
        float t;
        asm("tanh.approx.f32 %0, %1;" : "=f"(t) : "f"(fmaf(a, v, c)));
        accv += t;
    }
    out[(size_t)b * E_DIM + e] = accv * (1.0f / K_SAMP);
}

// ---------------------------------------------------------------------------
extern "C" void kernel_launch(void* const* d_in, const int* in_sizes, int n_in,
                              void* d_out, int out_size)
{
    const float* features = (const float*)d_in[0];
    const float* W        = (const float*)d_in[1];
    const float* bias     = (const float*)d_in[2];
    const float* gamma    = (const float*)d_in[3];
    const float* beta     = (const float*)d_in[4];
    const int*   sidx     = (const int*)d_in[5];
    float*       out      = (float*)d_out;

    cudaFuncSetAttribute(gemm_mma_kernel,
                         cudaFuncAttributeMaxDynamicSharedMemorySize, SMEM_TOTAL);

    prep_w_kernel<<<128, 256>>>(W);
    gemm_mma_kernel<<<NTILES, 512, SMEM_TOTAL>>>(features, bias);
    finalize_stats_kernel<<<128, 256>>>(gamma, beta);
    gather_mean_kernel<<<B_ROWS, E_DIM>>>(sidx, out);
}

// round 6
// speedup vs baseline: 2.4537x; 1.1362x over previous
#include <cuda_runtime.h>
#include <cuda_fp16.h>
#include <cstdint>

// ---------------------------------------------------------------------------
// Problem constants
// ---------------------------------------------------------------------------
#define U_NODES 200000
#define F_DIM   256
#define E_DIM   128
#define B_ROWS  20000
#define K_SAMP  33
#define BN_EPS  1e-5f

#define TM      128
#define KC      64                        // K chunk (fp16 elems)
#define NCH     (F_DIM / KC)              // 4
#define NTILES  ((U_NODES + TM - 1) / TM) // 1563

// SMEM layout (bytes, dynamic)
#define OFF_BIAS   0
#define OFF_W      1024                       // W hi 64KB, W lo 64KB (whole K)
#define OFF_A      (OFF_W + 131072)           // 2 stages x 16KB (fp16 A)
#define SMEM_TOTAL (OFF_A + 32768)            // 164864

// ---------------------------------------------------------------------------
// Device scratch
// ---------------------------------------------------------------------------
__device__ float g_h[(size_t)U_NODES * E_DIM];
__device__ float g_part[NTILES * 2 * E_DIM];
__device__ float g_ab[2 * E_DIM];
// W images: [K=256][N=128] fp16 row-major (256B rows), 16B-col XOR-swizzle by (k&7)
__device__ __align__(16) __half g_wh[F_DIM * E_DIM];
__device__ __align__(16) __half g_wl[F_DIM * E_DIM];

// ---------------------------------------------------------------------------
// Helpers
// ---------------------------------------------------------------------------
__device__ __forceinline__ uint32_t smem_u32(const void* p) {
    uint32_t a;
    asm("{ .reg .u64 t; cvta.to.shared.u64 t, %1; cvt.u32.u64 %0, t; }"
        : "=r"(a) : "l"(p));
    return a;
}
__device__ __forceinline__ void sts128(uint32_t addr, uint32_t a, uint32_t b,
                                       uint32_t c, uint32_t d) {
    asm volatile("st.shared.v4.b32 [%0], {%1, %2, %3, %4};"
                 :: "r"(addr), "r"(a), "r"(b), "r"(c), "r"(d) : "memory");
}
__device__ __forceinline__ void cp16(uint32_t s, const void* g) {
    asm volatile("cp.async.cg.shared.global [%0], [%1], 16;"
                 :: "r"(s), "l"(g) : "memory");
}
__device__ __forceinline__ void cp_commit() {
    asm volatile("cp.async.commit_group;" ::: "memory");
}
__device__ __forceinline__ void cp_wait0() {
    asm volatile("cp.async.wait_group 0;" ::: "memory");
}
__device__ __forceinline__ void ldmx4(uint32_t addr, uint32_t* r) {
    asm volatile("ldmatrix.sync.aligned.m8n8.x4.shared.b16 {%0,%1,%2,%3}, [%4];"
                 : "=r"(r[0]), "=r"(r[1]), "=r"(r[2]), "=r"(r[3]) : "r"(addr));
}
__device__ __forceinline__ void ldmx4t(uint32_t addr, uint32_t* r) {
    asm volatile("ldmatrix.sync.aligned.m8n8.x4.trans.shared.b16 {%0,%1,%2,%3}, [%4];"
                 : "=r"(r[0]), "=r"(r[1]), "=r"(r[2]), "=r"(r[3]) : "r"(addr));
}
__device__ __forceinline__ void mma_f16(float* d, const uint32_t* a,
                                        uint32_t b0, uint32_t b1) {
    asm volatile(
        "mma.sync.aligned.m16n8k16.row.col.f32.f16.f16.f32 "
        "{%0,%1,%2,%3}, {%4,%5,%6,%7}, {%8,%9}, {%0,%1,%2,%3};"
        : "+f"(d[0]), "+f"(d[1]), "+f"(d[2]), "+f"(d[3])
        : "r"(a[0]), "r"(a[1]), "r"(a[2]), "r"(a[3]), "r"(b0), "r"(b1));
}
// pack two fp32 into fp16x2 (RN)
__device__ __forceinline__ uint32_t pack_f16x2(float lo, float hi) {
    uint32_t r;
    asm("cvt.rn.f16x2.f32 %0, %1, %2;" : "=r"(r) : "f"(hi), "f"(lo));
    return r;
}

// ---------------------------------------------------------------------------
// Kernel 0: W [256,128] fp32 -> fp16 hi/lo images, [K][N] row-major, swizzled.
// hi = RN16(w), lo = RN16(w - hi): W represented to ~2^-22.
// byte offset = k*256 + ((n*2) ^ ((k&7)<<4))
// ---------------------------------------------------------------------------
__global__ void prep_w_kernel(const float* __restrict__ W) {
    int idx = blockIdx.x * 256 + threadIdx.x;    // 0..32767
    int k = idx >> 7;
    int n = idx & 127;
    float w = W[idx];
    __half hi = __float2half_rn(w);
    __half lo = __float2half_rn(w - __half2float(hi));
    uint32_t off = (uint32_t)k * 256 + (((uint32_t)n * 2) ^ ((k & 7) << 4));
    g_wh[off >> 1] = hi;
    g_wl[off >> 1] = lo;
}

// ---------------------------------------------------------------------------
// Kernel 1: h = A @ W + b via mma.sync fp16, 2-term split (A fp16, W hi+lo),
// fused col stats. 512 threads = 16 warps (4x4 warp grid of 32x32 tiles).
// W resident in SMEM; A pipelined (STS c+1, LDG c+2, MMA c).
// ---------------------------------------------------------------------------
__global__ void __launch_bounds__(512, 1)
gemm_mma_kernel(const float* __restrict__ A, const float* __restrict__ bias)
{
    extern __shared__ char smem[];
    const uint32_t sm = smem_u32(smem);
    const int tid  = threadIdx.x;
    const int wid  = tid >> 5;
    const int lane = tid & 31;
    const int row0 = blockIdx.x * TM;
    const int warp_m = wid >> 2;          // 0..3 -> 32-row band
    const int warp_n = wid & 3;           // 0..3 -> 32-col band

    float* sbias = (float*)(smem + OFF_BIAS);
    if (tid < 128) sbias[tid] = bias[tid];

    // ---- load full W (hi+lo, 128KB) once via cp.async ----
    {
        const char* srcH = (const char*)g_wh;
        const char* srcL = (const char*)g_wl;
        const uint32_t dH = sm + OFF_W;
        const uint32_t dL = sm + OFF_W + 65536;
#pragma unroll
        for (int j = 0; j < 8; j++) {
            const int u = tid + j * 512;          // 16B units, 0..4095
            cp16(dH + u * 16, srcH + (size_t)u * 16);
            cp16(dL + u * 16, srcL + (size_t)u * 16);
        }
        cp_commit();
    }

    // ---- producer setup: thread -> (row, 16-float quarter) ----
    const int pr = tid >> 2;             // 0..127
    const int pq = tid & 3;              // quarter within 64-col chunk
    const bool pvalid = (row0 + pr) < U_NODES;
    const float* aptr = A + (size_t)(row0 + pr) * F_DIM + pq * 16;
    uint32_t a_sts[2];
#pragma unroll
    for (int i = 0; i < 2; i++)
        a_sts[i] = (uint32_t)pr * 128 +
                   (((uint32_t)(pq * 32 + i * 16)) ^ ((pr & 7) << 4));

    float fA[16];
    auto lda = [&](int c) {
        if (pvalid) {
            const float4* p = (const float4*)(aptr + c * KC);
#pragma unroll
            for (int i = 0; i < 4; i++) {
                float4 v = p[i];
                fA[i * 4 + 0] = v.x; fA[i * 4 + 1] = v.y;
                fA[i * 4 + 2] = v.z; fA[i * 4 + 3] = v.w;
            }
        } else {
#pragma unroll
            for (int i = 0; i < 16; i++) fA[i] = 0.f;
        }
    };
    auto stsA = [&](int stage) {
        uint32_t hw[8];
#pragma unroll
        for (int p = 0; p < 8; p++)
            hw[p] = pack_f16x2(fA[2 * p], fA[2 * p + 1]);
        const uint32_t ah = sm + OFF_A + stage * 16384;
        sts128(ah + a_sts[0], hw[0], hw[1], hw[2], hw[3]);
        sts128(ah + a_sts[1], hw[4], hw[5], hw[6], hw[7]);
    };

    // ---- MMA-side precomputed addressing ----
    uint32_t aoff[2], axor[2];
#pragma unroll
    for (int am = 0; am < 2; am++) {
        int r = warp_m * 32 + am * 16 + (lane & 15);
        aoff[am] = (uint32_t)r * 128;
        axor[am] = (uint32_t)(r & 7) << 4;
    }
    const uint32_t acolb = (uint32_t)(lane >> 4) * 16;
    const int bk = lane & 15;
    uint32_t bcol[2];
#pragma unroll
    for (int nb = 0; nb < 2; nb++)
        bcol[nb] = (((uint32_t)(warp_n * 32 + nb * 16 + (lane >> 4) * 8) * 2)
                    ^ ((bk & 7) << 4));
    const uint32_t brow = (uint32_t)bk * 256;

    float acc[2][4][4];
#pragma unroll
    for (int am = 0; am < 2; am++)
#pragma unroll
        for (int na = 0; na < 4; na++)
#pragma unroll
            for (int q = 0; q < 4; q++) acc[am][na][q] = 0.f;

    // ---- prologue ----
    lda(0);
    stsA(0);
    lda(1);
    cp_wait0();              // W resident
    __syncthreads();

    for (int c = 0; c < NCH; c++) {
        const int stage = c & 1;
        if (c + 1 < NCH) stsA(stage ^ 1);    // convert+store chunk c+1
        if (c + 2 < NCH) lda(c + 2);         // issue LDGs for chunk c+2

        const uint32_t Ahb = sm + OFF_A + stage * 16384;
        const uint32_t Whb = sm + OFF_W + (uint32_t)c * 16384;
        const uint32_t Wlb = Whb + 65536;

#pragma unroll
        for (int ks = 0; ks < 4; ks++) {
            uint32_t ah[2][4];
#pragma unroll
            for (int am = 0; am < 2; am++)
                ldmx4(Ahb + aoff[am] + ((acolb + ks * 32) ^ axor[am]), ah[am]);
#pragma unroll
            for (int nb = 0; nb < 2; nb++) {
                uint32_t bh[4], bl[4];
                const uint32_t bo = (uint32_t)ks * 4096 + brow + bcol[nb];
                ldmx4t(Whb + bo, bh);
                ldmx4t(Wlb + bo, bl);
#pragma unroll
                for (int am = 0; am < 2; am++)
#pragma unroll
                    for (int half = 0; half < 2; half++) {
                        float* d = acc[am][nb * 2 + half];
                        mma_f16(d, ah[am], bh[half * 2], bh[half * 2 + 1]);
                        mma_f16(d, ah[am], bl[half * 2], bl[half * 2 + 1]);
                    }
            }
        }
        __syncthreads();
    }

    // ---- epilogue: stage acc to smem (reuse W area), store h + stats ----
    float* ht = (float*)(smem + OFF_W);    // [128][129] fp32 (66KB)
#pragma unroll
    for (int am = 0; am < 2; am++) {
        const int r0 = warp_m * 32 + am * 16 + (lane >> 2);
#pragma unroll
        for (int na = 0; na < 4; na++) {
            const int col = warp_n * 32 + na * 8 + (lane & 3) * 2;
            ht[r0 * 129 + col]           = acc[am][na][0];
            ht[r0 * 129 + col + 1]       = acc[am][na][1];
            ht[(r0 + 8) * 129 + col]     = acc[am][na][2];
            ht[(r0 + 8) * 129 + col + 1] = acc[am][na][3];
        }
    }
    __syncthreads();

    const int validRows = (U_NODES - row0 < TM) ? (U_NODES - row0) : TM;

    // store h (+bias): thread -> (row, 32-col quarter)
    {
        const int r = tid >> 2;
        const int q = tid & 3;
        if (r < validRows) {
            float* dst = g_h + (size_t)(row0 + r) * E_DIM + q * 32;
            const float* src = ht + r * 129 + q * 32;
            const float* bb  = sbias + q * 32;
#pragma unroll
            for (int j = 0; j < 8; j++) {
                float4 v = make_float4(src[4 * j] + bb[4 * j],
                                       src[4 * j + 1] + bb[4 * j + 1],
                                       src[4 * j + 2] + bb[4 * j + 2],
                                       src[4 * j + 3] + bb[4 * j + 3]);
                *(float4*)(dst + 4 * j) = v;
            }
        }
    }

    // column stats: 4 row-bands x 128 cols, then 4-way combine
    {
        float* red_s = (float*)(smem + OFF_A);          // 512 floats
        float* red_q = red_s + 512;
        const int e = tid & 127;
        const int band = tid >> 7;                      // 0..3
        const float be = sbias[e];
        float s = 0.f, q = 0.f;
        const int rEnd = min(band * 32 + 32, validRows);
        for (int r = band * 32; r < rEnd; r++) {
            float x = ht[r * 129 + e] + be;
            s += x; q += x * x;
        }
        red_s[band * 128 + e] = s;
        red_q[band * 128 + e] = q;
        __syncthreads();
        if (tid < 128) {
            float ts = red_s[tid] + red_s[128 + tid] +
                       red_s[256 + tid] + red_s[384 + tid];
            float tq = red_q[tid] + red_q[128 + tid] +
                       red_q[256 + tid] + red_q[384 + tid];
            g_part[blockIdx.x * 256 + tid]       = ts;
            g_part[blockIdx.x * 256 + 128 + tid] = tq;
        }
    }
}

// ---------------------------------------------------------------------------
// Kernel 2: finalize BN stats (one block per embedding column)
// ---------------------------------------------------------------------------
__global__ void finalize_stats_kernel(const float* __restrict__ gamma,
                                      const float* __restrict__ beta)
{
    __shared__ float ss[256], sq[256];
    const int e = blockIdx.x;
    const int t = threadIdx.x;
    float s = 0.f, q = 0.f;
    for (int i = t; i < NTILES; i += 256) {
        s += g_part[i * 256 + e];
        q += g_part[i * 256 + 128 + e];
    }
    ss[t] = s; sq[t] = q;
    __syncthreads();
    for (int st = 128; st > 0; st >>= 1) {
        if (t < st) { ss[t] += ss[t + st]; sq[t] += sq[t + st]; }
        __syncthreads();
    }
    if (t == 0) {
        const float mu  = ss[0] * (1.0f / U_NODES);
        const float var = sq[0] * (1.0f / U_NODES) - mu * mu;
        const float a   = gamma[e] * rsqrtf(var + BN_EPS);
        g_ab[e]         = a;
        g_ab[E_DIM + e] = beta[e] - mu * a;
    }
}

// ---------------------------------------------------------------------------
// Kernel 3: out[b] = mean_k tanh(a * h[idx[b,k]] + c)   (tanh.approx.f32)
// ---------------------------------------------------------------------------
__global__ void __launch_bounds__(128)
gather_mean_kernel(const int* __restrict__ idx, float* __restrict__ out)
{
    __shared__ int sidx[K_SAMP];
    const int b = blockIdx.x;
    const int e = threadIdx.x;
    if (e < K_SAMP) sidx[e] = idx[b * K_SAMP + e];
    __syncthreads();

    const float a = g_ab[e];
    const float c = g_ab[E_DIM + e];
    float accv = 0.f;
#pragma unroll
    for (int k = 0; k < K_SAMP; k++) {
        const float v = __ldg(g_h + (size_t)sidx[k] * E_DIM + e);
        float t;
        asm("tanh.approx.f32 %0, %1;" : "=f"(t) : "f"(fmaf(a, v, c)));
        accv += t;
    }
    out[(size_t)b * E_DIM + e] = accv * (1.0f / K_SAMP);
}

// ---------------------------------------------------------------------------
extern "C" void kernel_launch(void* const* d_in, const int* in_sizes, int n_in,
                              void* d_out, int out_size)
{
    const float* features = (const float*)d_in[0];
    const float* W        = (const float*)d_in[1];
    const float* bias     = (const float*)d_in[2];
    const float* gamma    = (const float*)d_in[3];
    const float* beta     = (const float*)d_in[4];
    const int*   sidx     = (const int*)d_in[5];
    float*       out      = (float*)d_out;

    cudaFuncSetAttribute(gemm_mma_kernel,
                         cudaFuncAttributeMaxDynamicSharedMemorySize, SMEM_TOTAL);

    prep_w_kernel<<<128, 256>>>(W);
    gemm_mma_kernel<<<NTILES, 512, SMEM_TOTAL>>>(features, bias);
    finalize_stats_kernel<<<128, 256>>>(gamma, beta);
    gather_mean_kernel<<<B_ROWS, E_DIM>>>(sidx, out);
}

// round 8
// speedup vs baseline: 3.5576x; 1.4499x over previous
#include <cuda_runtime.h>
#include <cuda_fp16.h>
#include <cstdint>

// ---------------------------------------------------------------------------
// Problem constants
// ---------------------------------------------------------------------------
#define U_NODES 200000
#define F_DIM   256
#define E_DIM   128
#define B_ROWS  20000
#define K_SAMP  33
#define BN_EPS  1e-5f

#define TM      128
#define KC      64                        // K chunk (fp16 elems)
#define NCH     (F_DIM / KC)              // 4
#define NTILES  ((U_NODES + TM - 1) / TM) // 1563

// SMEM layout (bytes, dynamic)
#define OFF_BIAS   0                          // 512 B
#define OFF_W      512                        // 64 KB (fp16 W, whole K)
#define OFF_A      (OFF_W + 65536)            // 2 stages x 16KB (fp16 A)
#define SMEM_TOTAL (OFF_A + 32768)            // 98816 -> 2 CTAs/SM

// ---------------------------------------------------------------------------
// Device scratch
// ---------------------------------------------------------------------------
__device__ float g_h[(size_t)U_NODES * E_DIM];
__device__ float g_part[NTILES * 2 * E_DIM];
__device__ __align__(16) float g_ab[2 * E_DIM];
// W image: [K=256 rows][N=128] fp16 (256B rows), 16B-col XOR-swizzle by (k&7)
__device__ __align__(16) __half g_wh[F_DIM * E_DIM];

// ---------------------------------------------------------------------------
// Helpers
// ---------------------------------------------------------------------------
__device__ __forceinline__ uint32_t smem_u32(const void* p) {
    uint32_t a;
    asm("{ .reg .u64 t; cvta.to.shared.u64 t, %1; cvt.u32.u64 %0, t; }"
        : "=r"(a) : "l"(p));
    return a;
}
__device__ __forceinline__ void sts128(uint32_t addr, uint32_t a, uint32_t b,
                                       uint32_t c, uint32_t d) {
    asm volatile("st.shared.v4.b32 [%0], {%1, %2, %3, %4};"
                 :: "r"(addr), "r"(a), "r"(b), "r"(c), "r"(d) : "memory");
}
__device__ __forceinline__ void cp16(uint32_t s, const void* g) {
    asm volatile("cp.async.cg.shared.global [%0], [%1], 16;"
                 :: "r"(s), "l"(g) : "memory");
}
__device__ __forceinline__ void cp_commit() {
    asm volatile("cp.async.commit_group;" ::: "memory");
}
__device__ __forceinline__ void cp_wait0() {
    asm volatile("cp.async.wait_group 0;" ::: "memory");
}
__device__ __forceinline__ void ldmx4(uint32_t addr, uint32_t* r) {
    asm volatile("ldmatrix.sync.aligned.m8n8.x4.shared.b16 {%0,%1,%2,%3}, [%4];"
                 : "=r"(r[0]), "=r"(r[1]), "=r"(r[2]), "=r"(r[3]) : "r"(addr));
}
__device__ __forceinline__ void ldmx4t(uint32_t addr, uint32_t* r) {
    asm volatile("ldmatrix.sync.aligned.m8n8.x4.trans.shared.b16 {%0,%1,%2,%3}, [%4];"
                 : "=r"(r[0]), "=r"(r[1]), "=r"(r[2]), "=r"(r[3]) : "r"(addr));
}
__device__ __forceinline__ void mma_f16(float* d, const uint32_t* a,
                                        uint32_t b0, uint32_t b1) {
    asm volatile(
        "mma.sync.aligned.m16n8k16.row.col.f32.f16.f16.f32 "
        "{%0,%1,%2,%3}, {%4,%5,%6,%7}, {%8,%9}, {%0,%1,%2,%3};"
        : "+f"(d[0]), "+f"(d[1]), "+f"(d[2]), "+f"(d[3])
        : "r"(a[0]), "r"(a[1]), "r"(a[2]), "r"(a[3]), "r"(b0), "r"(b1));
}
__device__ __forceinline__ uint32_t pack_f16x2(float lo, float hi) {
    uint32_t r;
    asm("cvt.rn.f16x2.f32 %0, %1, %2;" : "=r"(r) : "f"(hi), "f"(lo));
    return r;
}

// ---------------------------------------------------------------------------
// Kernel 0: W [256,128] fp32 -> fp16, [K][N] row-major, swizzled.
// byte offset = k*256 + ((n*2) ^ ((k&7)<<4))
// ---------------------------------------------------------------------------
__global__ void prep_w_kernel(const float* __restrict__ W) {
    int idx = blockIdx.x * 256 + threadIdx.x;    // 0..32767
    int k = idx >> 7;
    int n = idx & 127;
    uint32_t off = (uint32_t)k * 256 + (((uint32_t)n * 2) ^ ((k & 7) << 4));
    g_wh[off >> 1] = __float2half_rn(W[idx]);
}

// ---------------------------------------------------------------------------
// Kernel 1: h = A @ W + b via mma.sync fp16 (A fp16, W fp16), fused col stats.
// 512 threads = 16 warps (4x4 grid of 32x32 tiles), 2 CTAs/SM.
// Register-direct epilogue (STG.64 + shfl stats), no smem h tile.
// ---------------------------------------------------------------------------
__global__ void __launch_bounds__(512, 2)
gemm_mma_kernel(const float* __restrict__ A, const float* __restrict__ bias)
{
    extern __shared__ char smem[];
    const uint32_t sm = smem_u32(smem);
    const int tid  = threadIdx.x;
    const int wid  = tid >> 5;
    const int lane = tid & 31;
    const int row0 = blockIdx.x * TM;
    const int warp_m = wid >> 2;          // 0..3 -> 32-row band
    const int warp_n = wid & 3;           // 0..3 -> 32-col band

    float* sbias = (float*)(smem + OFF_BIAS);
    if (tid < 128) sbias[tid] = bias[tid];

    // ---- load full W (64KB fp16) once via cp.async ----
    {
        const char* src = (const char*)g_wh;
        const uint32_t dst = sm + OFF_W;
#pragma unroll
        for (int j = 0; j < 8; j++) {
            const int u = tid + j * 512;          // 16B units, 0..4095
            cp16(dst + u * 16, src + (size_t)u * 16);
        }
        cp_commit();
    }

    // ---- producer mapping: thread -> (row, 16-float quarter) ----
    const int pr = tid >> 2;             // 0..127
    const int pq = tid & 3;
    const bool pvalid = (row0 + pr) < U_NODES;
    const float* aptr = A + (size_t)(row0 + pr) * F_DIM + pq * 16;
    uint32_t a_sts[2];
#pragma unroll
    for (int i = 0; i < 2; i++)
        a_sts[i] = (uint32_t)pr * 128 +
                   (((uint32_t)(pq * 32 + i * 16)) ^ ((pr & 7) << 4));

    // ---- MMA-side addressing ----
    uint32_t aoff[2], axor[2];
#pragma unroll
    for (int am = 0; am < 2; am++) {
        int r = warp_m * 32 + am * 16 + (lane & 15);
        aoff[am] = (uint32_t)r * 128;
        axor[am] = (uint32_t)(r & 7) << 4;
    }
    const uint32_t acolb = (uint32_t)(lane >> 4) * 16;
    const int bk = lane & 15;
    uint32_t bcol[2];
#pragma unroll
    for (int nb = 0; nb < 2; nb++)
        bcol[nb] = (((uint32_t)(warp_n * 32 + nb * 16 + (lane >> 4) * 8) * 2)
                    ^ ((bk & 7) << 4));
    const uint32_t brow = (uint32_t)bk * 256;

    float acc[2][4][4];
#pragma unroll
    for (int am = 0; am < 2; am++)
#pragma unroll
        for (int na = 0; na < 4; na++)
#pragma unroll
            for (int q = 0; q < 4; q++) acc[am][na][q] = 0.f;

    cp_wait0();
    __syncthreads();

    for (int c = 0; c < NCH; c++) {
        const int stage = c & 1;

        // producer: LDG 16 floats -> fp16x2 -> STS (other CTA's MMA covers latency)
        {
            uint32_t hw[8];
            if (pvalid) {
                const float4* p = (const float4*)(aptr + c * KC);
#pragma unroll
                for (int i = 0; i < 4; i++) {
                    float4 v = p[i];
                    hw[2 * i]     = pack_f16x2(v.x, v.y);
                    hw[2 * i + 1] = pack_f16x2(v.z, v.w);
                }
            } else {
#pragma unroll
                for (int i = 0; i < 8; i++) hw[i] = 0u;
            }
            const uint32_t ab = sm + OFF_A + stage * 16384;
            sts128(ab + a_sts[0], hw[0], hw[1], hw[2], hw[3]);
            sts128(ab + a_sts[1], hw[4], hw[5], hw[6], hw[7]);
        }
        __syncthreads();

        const uint32_t Ahb = sm + OFF_A + stage * 16384;
        const uint32_t Whb = sm + OFF_W + (uint32_t)c * 16384;
#pragma unroll
        for (int ks = 0; ks < 4; ks++) {
            uint32_t ah[2][4];
#pragma unroll
            for (int am = 0; am < 2; am++)
                ldmx4(Ahb + aoff[am] + ((acolb + ks * 32) ^ axor[am]), ah[am]);
#pragma unroll
            for (int nb = 0; nb < 2; nb++) {
                uint32_t bh[4];
                ldmx4t(Whb + (uint32_t)ks * 4096 + brow + bcol[nb], bh);
#pragma unroll
                for (int am = 0; am < 2; am++) {
                    mma_f16(acc[am][nb * 2],     ah[am], bh[0], bh[1]);
                    mma_f16(acc[am][nb * 2 + 1], ah[am], bh[2], bh[3]);
                }
            }
        }
        // no trailing sync needed: STS(c+1) targets the other stage and is
        // ordered after this warp's MMA(c); sync(c) already guaranteed all
        // warps finished MMA(c-1) (the last reader of that buffer).
    }

    // ---- epilogue: direct STG + register/shuffle column stats ----
    const int colb = warp_n * 32 + (lane & 3) * 2;   // this thread's col base
    float2 b2[4];
#pragma unroll
    for (int na = 0; na < 4; na++)
        b2[na] = *(const float2*)&sbias[colb + na * 8];

    float s0[4], s1[4], q0[4], q1[4];
#pragma unroll
    for (int na = 0; na < 4; na++) { s0[na] = s1[na] = q0[na] = q1[na] = 0.f; }

#pragma unroll
    for (int am = 0; am < 2; am++) {
        const int rA = warp_m * 32 + am * 16 + (lane >> 2);
#pragma unroll
        for (int half = 0; half < 2; half++) {
            const int r = rA + half * 8;
            const bool v = (row0 + r) < U_NODES;
            float* dst = g_h + (size_t)(row0 + r) * E_DIM + colb;
#pragma unroll
            for (int na = 0; na < 4; na++) {
                float x0 = acc[am][na][half * 2]     + b2[na].x;
                float x1 = acc[am][na][half * 2 + 1] + b2[na].y;
                if (v) {
                    *(float2*)(dst + na * 8) = make_float2(x0, x1);
                    s0[na] += x0; s1[na] += x1;
                    q0[na] += x0 * x0; q1[na] += x1 * x1;
                }
            }
        }
    }
    // reduce over the 8 lanes sharing (lane&3): xor 4, 8, 16
#pragma unroll
    for (int m = 4; m <= 16; m <<= 1) {
#pragma unroll
        for (int na = 0; na < 4; na++) {
            s0[na] += __shfl_xor_sync(0xFFFFFFFFu, s0[na], m);
            s1[na] += __shfl_xor_sync(0xFFFFFFFFu, s1[na], m);
            q0[na] += __shfl_xor_sync(0xFFFFFFFFu, q0[na], m);
            q1[na] += __shfl_xor_sync(0xFFFFFFFFu, q1[na], m);
        }
    }
    __syncthreads();                       // MMA reads of A bufs done
    float* red_s = (float*)(smem + OFF_A);          // 4 x 128 floats
    float* red_q = red_s + 512;
    if (lane < 4) {
#pragma unroll
        for (int na = 0; na < 4; na++) {
            const int col = warp_n * 32 + na * 8 + lane * 2;
            red_s[warp_m * 128 + col]     = s0[na];
            red_s[warp_m * 128 + col + 1] = s1[na];
            red_q[warp_m * 128 + col]     = q0[na];
            red_q[warp_m * 128 + col + 1] = q1[na];
        }
    }
    __syncthreads();
    if (tid < 128) {
        float ts = red_s[tid] + red_s[128 + tid] +
                   red_s[256 + tid] + red_s[384 + tid];
        float tq = red_q[tid] + red_q[128 + tid] +
                   red_q[256 + tid] + red_q[384 + tid];
        g_part[blockIdx.x * 256 + tid]       = ts;
        g_part[blockIdx.x * 256 + 128 + tid] = tq;
    }
}

// ---------------------------------------------------------------------------
// Kernel 2: finalize BN stats (one block per embedding column)
// ---------------------------------------------------------------------------
__global__ void finalize_stats_kernel(const float* __restrict__ gamma,
                                      const float* __restrict__ beta)
{
    __shared__ float ss[256], sq[256];
    const int e = blockIdx.x;
    const int t = threadIdx.x;
    float s = 0.f, q = 0.f;
    for (int i = t; i < NTILES; i += 256) {
        s += g_part[i * 256 + e];
        q += g_part[i * 256 + 128 + e];
    }
    ss[t] = s; sq[t] = q;
    __syncthreads();
    for (int st = 128; st > 0; st >>= 1) {
        if (t < st) { ss[t] += ss[t + st]; sq[t] += sq[t + st]; }
        __syncthreads();
    }
    if (t == 0) {
        const float mu  = ss[0] * (1.0f / U_NODES);
        const float var = sq[0] * (1.0f / U_NODES) - mu * mu;
        const float a   = gamma[e] * rsqrtf(var + BN_EPS);
        g_ab[e]         = a;
        g_ab[E_DIM + e] = beta[e] - mu * a;
    }
}

// ---------------------------------------------------------------------------
// Kernel 3: out[b] = mean_k tanh(a * h[idx[b,k]] + c)
// one warp per output row, float4 per lane (warp covers the full 512B row)
// ---------------------------------------------------------------------------
__global__ void __launch_bounds__(128)
gather_mean_kernel(const int* __restrict__ idx, float* __restrict__ out)
{
    __shared__ int sidx[4 * K_SAMP];
    const int b0 = blockIdx.x * 4;
    const int tid = threadIdx.x;
    const int w = tid >> 5;
    const int lane = tid & 31;
    // 132 indices, 128 threads: strided load (R7 bug: tail never written)
    for (int i = tid; i < 4 * K_SAMP; i += 128)
        sidx[i] = idx[b0 * K_SAMP + i];
    __syncthreads();

    const float4 a4 = *(const float4*)&g_ab[lane * 4];
    const float4 c4 = *(const float4*)&g_ab[E_DIM + lane * 4];
    float4 acc = make_float4(0.f, 0.f, 0.f, 0.f);
    const int* myidx = sidx + w * K_SAMP;
#pragma unroll 3
    for (int k = 0; k < K_SAMP; k++) {
        const float4 v = __ldg((const float4*)(g_h + (size_t)myidx[k] * E_DIM)
                               + lane);
        float t0, t1, t2, t3;
        asm("tanh.approx.f32 %0, %1;" : "=f"(t0) : "f"(fmaf(a4.x, v.x, c4.x)));
        asm("tanh.approx.f32 %0, %1;" : "=f"(t1) : "f"(fmaf(a4.y, v.y, c4.y)));
        asm("tanh.approx.f32 %0, %1;" : "=f"(t2) : "f"(fmaf(a4.z, v.z, c4.z)));
        asm("tanh.approx.f32 %0, %1;" : "=f"(t3) : "f"(fmaf(a4.w, v.w, c4.w)));
        acc.x += t0; acc.y += t1; acc.z += t2; acc.w += t3;
    }
    const float sc = 1.0f / K_SAMP;
    float4 o = make_float4(acc.x * sc, acc.y * sc, acc.z * sc, acc.w * sc);
    *(float4*)(out + (size_t)(b0 + w) * E_DIM + lane * 4) = o;
}

// ---------------------------------------------------------------------------
extern "C" void kernel_launch(void* const* d_in, const int* in_sizes, int n_in,
                              void* d_out, int out_size)
{
    const float* features = (const float*)d_in[0];
    const float* W        = (const float*)d_in[1];
    const float* bias     = (const float*)d_in[2];
    const float* gamma    = (const float*)d_in[3];
    const float* beta     = (const float*)d_in[4];
    const int*   sidx     = (const int*)d_in[5];
    float*       out      = (float*)d_out;

    cudaFuncSetAttribute(gemm_mma_kernel,
                         cudaFuncAttributeMaxDynamicSharedMemorySize, SMEM_TOTAL);

    prep_w_kernel<<<128, 256>>>(W);
    gemm_mma_kernel<<<NTILES, 512, SMEM_TOTAL>>>(features, bias);
    finalize_stats_kernel<<<128, 256>>>(gamma, beta);
    gather_mean_kernel<<<B_ROWS / 4, 128>>>(sidx, out);
}

// round 9
// speedup vs baseline: 4.0871x; 1.1489x over previous
#include <cuda_runtime.h>
#include <cuda_fp16.h>
#include <cstdint>

// ---------------------------------------------------------------------------
// Problem constants
// ---------------------------------------------------------------------------
#define U_NODES 200000
#define F_DIM   256
#define E_DIM   128
#define B_ROWS  20000
#define K_SAMP  33
#define BN_EPS  1e-5f

#define TM      128
#define KC      64                        // K chunk (fp16 elems)
#define NCH     (F_DIM / KC)              // 4
#define NTILES  ((U_NODES + TM - 1) / TM) // 1563

// SMEM layout (bytes, dynamic)
#define OFF_BIAS   0                          // 512 B
#define OFF_W      512                        // 64 KB (fp16 W, whole K)
#define OFF_A      (OFF_W + 65536)            // 2 stages x 16KB (fp16 A)
#define SMEM_TOTAL (OFF_A + 32768)            // 98816 -> 2 CTAs/SM

// ---------------------------------------------------------------------------
// Device scratch
// ---------------------------------------------------------------------------
__device__ __half g_h[(size_t)U_NODES * E_DIM];      // h in fp16 (51.2 MB)
__device__ float g_part[NTILES * 2 * E_DIM];
__device__ __align__(16) float g_ab[2 * E_DIM];
// W image: [K=256 rows][N=128] fp16 (256B rows), 16B-col XOR-swizzle by (k&7)
__device__ __align__(16) __half g_wh[F_DIM * E_DIM];

// ---------------------------------------------------------------------------
// Helpers
// ---------------------------------------------------------------------------
__device__ __forceinline__ uint32_t smem_u32(const void* p) {
    uint32_t a;
    asm("{ .reg .u64 t; cvta.to.shared.u64 t, %1; cvt.u32.u64 %0, t; }"
        : "=r"(a) : "l"(p));
    return a;
}
__device__ __forceinline__ void sts128(uint32_t addr, uint32_t a, uint32_t b,
                                       uint32_t c, uint32_t d) {
    asm volatile("st.shared.v4.b32 [%0], {%1, %2, %3, %4};"
                 :: "r"(addr), "r"(a), "r"(b), "r"(c), "r"(d) : "memory");
}
__device__ __forceinline__ void cp16(uint32_t s, const void* g) {
    asm volatile("cp.async.cg.shared.global [%0], [%1], 16;"
                 :: "r"(s), "l"(g) : "memory");
}
__device__ __forceinline__ void cp_commit() {
    asm volatile("cp.async.commit_group;" ::: "memory");
}
__device__ __forceinline__ void cp_wait0() {
    asm volatile("cp.async.wait_group 0;" ::: "memory");
}
__device__ __forceinline__ void ldmx4(uint32_t addr, uint32_t* r) {
    asm volatile("ldmatrix.sync.aligned.m8n8.x4.shared.b16 {%0,%1,%2,%3}, [%4];"
                 : "=r"(r[0]), "=r"(r[1]), "=r"(r[2]), "=r"(r[3]) : "r"(addr));
}
__device__ __forceinline__ void ldmx4t(uint32_t addr, uint32_t* r) {
    asm volatile("ldmatrix.sync.aligned.m8n8.x4.trans.shared.b16 {%0,%1,%2,%3}, [%4];"
                 : "=r"(r[0]), "=r"(r[1]), "=r"(r[2]), "=r"(r[3]) : "r"(addr));
}
__device__ __forceinline__ void mma_f16(float* d, const uint32_t* a,
                                        uint32_t b0, uint32_t b1) {
    asm volatile(
        "mma.sync.aligned.m16n8k16.row.col.f32.f16.f16.f32 "
        "{%0,%1,%2,%3}, {%4,%5,%6,%7}, {%8,%9}, {%0,%1,%2,%3};"
        : "+f"(d[0]), "+f"(d[1]), "+f"(d[2]), "+f"(d[3])
        : "r"(a[0]), "r"(a[1]), "r"(a[2]), "r"(a[3]), "r"(b0), "r"(b1));
}
__device__ __forceinline__ uint32_t pack_f16x2(float lo, float hi) {
    uint32_t r;
    asm("cvt.rn.f16x2.f32 %0, %1, %2;" : "=r"(r) : "f"(hi), "f"(lo));
    return r;
}

// ---------------------------------------------------------------------------
// Kernel 0: W [256,128] fp32 -> fp16, [K][N] row-major, swizzled.
// byte offset = k*256 + ((n*2) ^ ((k&7)<<4))
// ---------------------------------------------------------------------------
__global__ void prep_w_kernel(const float* __restrict__ W) {
    int idx = blockIdx.x * 256 + threadIdx.x;    // 0..32767
    int k = idx >> 7;
    int n = idx & 127;
    uint32_t off = (uint32_t)k * 256 + (((uint32_t)n * 2) ^ ((k & 7) << 4));
    g_wh[off >> 1] = __float2half_rn(W[idx]);
}

// ---------------------------------------------------------------------------
// Kernel 1: h = A @ W + b via mma.sync fp16, fused col stats, h stored fp16.
// 512 threads = 16 warps (4x4 grid of 32x32 tiles), 2 CTAs/SM.
// ---------------------------------------------------------------------------
__global__ void __launch_bounds__(512, 2)
gemm_mma_kernel(const float* __restrict__ A, const float* __restrict__ bias)
{
    extern __shared__ char smem[];
    const uint32_t sm = smem_u32(smem);
    const int tid  = threadIdx.x;
    const int wid  = tid >> 5;
    const int lane = tid & 31;
    const int row0 = blockIdx.x * TM;
    const int warp_m = wid >> 2;          // 0..3 -> 32-row band
    const int warp_n = wid & 3;           // 0..3 -> 32-col band

    float* sbias = (float*)(smem + OFF_BIAS);
    if (tid < 128) sbias[tid] = bias[tid];

    // ---- load full W (64KB fp16) once via cp.async ----
    {
        const char* src = (const char*)g_wh;
        const uint32_t dst = sm + OFF_W;
#pragma unroll
        for (int j = 0; j < 8; j++) {
            const int u = tid + j * 512;          // 16B units, 0..4095
            cp16(dst + u * 16, src + (size_t)u * 16);
        }
        cp_commit();
    }

    // ---- producer mapping: thread -> (row, 16-float quarter) ----
    const int pr = tid >> 2;             // 0..127
    const int pq = tid & 3;
    const bool pvalid = (row0 + pr) < U_NODES;
    const float* aptr = A + (size_t)(row0 + pr) * F_DIM + pq * 16;
    uint32_t a_sts[2];
#pragma unroll
    for (int i = 0; i < 2; i++)
        a_sts[i] = (uint32_t)pr * 128 +
                   (((uint32_t)(pq * 32 + i * 16)) ^ ((pr & 7) << 4));

    // ---- MMA-side addressing ----
    uint32_t aoff[2], axor[2];
#pragma unroll
    for (int am = 0; am < 2; am++) {
        int r = warp_m * 32 + am * 16 + (lane & 15);
        aoff[am] = (uint32_t)r * 128;
        axor[am] = (uint32_t)(r & 7) << 4;
    }
    const uint32_t acolb = (uint32_t)(lane >> 4) * 16;
    const int bk = lane & 15;
    uint32_t bcol[2];
#pragma unroll
    for (int nb = 0; nb < 2; nb++)
        bcol[nb] = (((uint32_t)(warp_n * 32 + nb * 16 + (lane >> 4) * 8) * 2)
                    ^ ((bk & 7) << 4));
    const uint32_t brow = (uint32_t)bk * 256;

    float acc[2][4][4];
#pragma unroll
    for (int am = 0; am < 2; am++)
#pragma unroll
        for (int na = 0; na < 4; na++)
#pragma unroll
            for (int q = 0; q < 4; q++) acc[am][na][q] = 0.f;

    cp_wait0();
    __syncthreads();

    for (int c = 0; c < NCH; c++) {
        const int stage = c & 1;

        // producer: LDG 16 floats -> fp16x2 -> STS (other CTA's MMA covers latency)
        {
            uint32_t hw[8];
            if (pvalid) {
                const float4* p = (const float4*)(aptr + c * KC);
#pragma unroll
                for (int i = 0; i < 4; i++) {
                    float4 v = p[i];
                    hw[2 * i]     = pack_f16x2(v.x, v.y);
                    hw[2 * i + 1] = pack_f16x2(v.z, v.w);
                }
            } else {
#pragma unroll
                for (int i = 0; i < 8; i++) hw[i] = 0u;
            }
            const uint32_t ab = sm + OFF_A + stage * 16384;
            sts128(ab + a_sts[0], hw[0], hw[1], hw[2], hw[3]);
            sts128(ab + a_sts[1], hw[4], hw[5], hw[6], hw[7]);
        }
        __syncthreads();

        const uint32_t Ahb = sm + OFF_A + stage * 16384;
        const uint32_t Whb = sm + OFF_W + (uint32_t)c * 16384;
#pragma unroll
        for (int ks = 0; ks < 4; ks++) {
            uint32_t ah[2][4];
#pragma unroll
            for (int am = 0; am < 2; am++)
                ldmx4(Ahb + aoff[am] + ((acolb + ks * 32) ^ axor[am]), ah[am]);
#pragma unroll
            for (int nb = 0; nb < 2; nb++) {
                uint32_t bh[4];
                ldmx4t(Whb + (uint32_t)ks * 4096 + brow + bcol[nb], bh);
#pragma unroll
                for (int am = 0; am < 2; am++) {
                    mma_f16(acc[am][nb * 2],     ah[am], bh[0], bh[1]);
                    mma_f16(acc[am][nb * 2 + 1], ah[am], bh[2], bh[3]);
                }
            }
        }
        // next STS targets the other stage; sync(c+1) orders it vs MMA(c+1)
    }

    // ---- epilogue: direct fp16 STG + register/shuffle column stats ----
    const int colb = warp_n * 32 + (lane & 3) * 2;   // this thread's col base
    float2 b2[4];
#pragma unroll
    for (int na = 0; na < 4; na++)
        b2[na] = *(const float2*)&sbias[colb + na * 8];

    float s0[4], s1[4], q0[4], q1[4];
#pragma unroll
    for (int na = 0; na < 4; na++) { s0[na] = s1[na] = q0[na] = q1[na] = 0.f; }

#pragma unroll
    for (int am = 0; am < 2; am++) {
        const int rA = warp_m * 32 + am * 16 + (lane >> 2);
#pragma unroll
        for (int half = 0; half < 2; half++) {
            const int r = rA + half * 8;
            const bool v = (row0 + r) < U_NODES;
            __half* dst = g_h + (size_t)(row0 + r) * E_DIM + colb;
#pragma unroll
            for (int na = 0; na < 4; na++) {
                float x0 = acc[am][na][half * 2]     + b2[na].x;
                float x1 = acc[am][na][half * 2 + 1] + b2[na].y;
                if (v) {
                    *(uint32_t*)(dst + na * 8) = pack_f16x2(x0, x1);
                    s0[na] += x0; s1[na] += x1;
                    q0[na] += x0 * x0; q1[na] += x1 * x1;
                }
            }
        }
    }
    // reduce over the 8 lanes sharing (lane&3): xor 4, 8, 16
#pragma unroll
    for (int m = 4; m <= 16; m <<= 1) {
#pragma unroll
        for (int na = 0; na < 4; na++) {
            s0[na] += __shfl_xor_sync(0xFFFFFFFFu, s0[na], m);
            s1[na] += __shfl_xor_sync(0xFFFFFFFFu, s1[na], m);
            q0[na] += __shfl_xor_sync(0xFFFFFFFFu, q0[na], m);
            q1[na] += __shfl_xor_sync(0xFFFFFFFFu, q1[na], m);
        }
    }
    __syncthreads();                       // MMA reads of A bufs done
    float* red_s = (float*)(smem + OFF_A);          // 4 x 128 floats
    float* red_q = red_s + 512;
    if (lane < 4) {
#pragma unroll
        for (int na = 0; na < 4; na++) {
            const int col = warp_n * 32 + na * 8 + lane * 2;
            red_s[warp_m * 128 + col]     = s0[na];
            red_s[warp_m * 128 + col + 1] = s1[na];
            red_q[warp_m * 128 + col]     = q0[na];
            red_q[warp_m * 128 + col + 1] = q1[na];
        }
    }
    __syncthreads();
    if (tid < 128) {
        float ts = red_s[tid] + red_s[128 + tid] +
                   red_s[256 + tid] + red_s[384 + tid];
        float tq = red_q[tid] + red_q[128 + tid] +
                   red_q[256 + tid] + red_q[384 + tid];
        g_part[blockIdx.x * 256 + tid]       = ts;
        g_part[blockIdx.x * 256 + 128 + tid] = tq;
    }
}

// ---------------------------------------------------------------------------
// Kernel 2: finalize BN stats (one block per embedding column)
// ---------------------------------------------------------------------------
__global__ void finalize_stats_kernel(const float* __restrict__ gamma,
                                      const float* __restrict__ beta)
{
    __shared__ float ss[256], sq[256];
    const int e = blockIdx.x;
    const int t = threadIdx.x;
    float s = 0.f, q = 0.f;
    for (int i = t; i < NTILES; i += 256) {
        s += g_part[i * 256 + e];
        q += g_part[i * 256 + 128 + e];
    }
    ss[t] = s; sq[t] = q;
    __syncthreads();
    for (int st = 128; st > 0; st >>= 1) {
        if (t < st) { ss[t] += ss[t + st]; sq[t] += sq[t + st]; }
        __syncthreads();
    }
    if (t == 0) {
        const float mu  = ss[0] * (1.0f / U_NODES);
        const float var = sq[0] * (1.0f / U_NODES) - mu * mu;
        const float a   = gamma[e] * rsqrtf(var + BN_EPS);
        g_ab[e]         = a;
        g_ab[E_DIM + e] = beta[e] - mu * a;
    }
}

// ---------------------------------------------------------------------------
// Kernel 3: out[b] = mean_k tanh(a * h[idx[b,k]] + c), h in fp16
// one warp per output row, uint2 (4 halves) per lane covers the 256B row
// ---------------------------------------------------------------------------
__global__ void __launch_bounds__(128)
gather_mean_kernel(const int* __restrict__ idx, float* __restrict__ out)
{
    __shared__ int sidx[4 * K_SAMP];
    const int b0 = blockIdx.x * 4;
    const int tid = threadIdx.x;
    const int w = tid >> 5;
    const int lane = tid & 31;
    for (int i = tid; i < 4 * K_SAMP; i += 128)
        sidx[i] = idx[b0 * K_SAMP + i];
    __syncthreads();

    const float4 a4 = *(const float4*)&g_ab[lane * 4];
    const float4 c4 = *(const float4*)&g_ab[E_DIM + lane * 4];
    float4 acc = make_float4(0.f, 0.f, 0.f, 0.f);
    const int* myidx = sidx + w * K_SAMP;
#pragma unroll 3
    for (int k = 0; k < K_SAMP; k++) {
        const uint2 u = __ldg((const uint2*)(g_h + (size_t)myidx[k] * E_DIM)
                              + lane);
        const float2 f0 = __half22float2(*(const half2*)&u.x);
        const float2 f1 = __half22float2(*(const half2*)&u.y);
        float t0, t1, t2, t3;
        asm("tanh.approx.f32 %0, %1;" : "=f"(t0) : "f"(fmaf(a4.x, f0.x, c4.x)));
        asm("tanh.approx.f32 %0, %1;" : "=f"(t1) : "f"(fmaf(a4.y, f0.y, c4.y)));
        asm("tanh.approx.f32 %0, %1;" : "=f"(t2) : "f"(fmaf(a4.z, f1.x, c4.z)));
        asm("tanh.approx.f32 %0, %1;" : "=f"(t3) : "f"(fmaf(a4.w, f1.y, c4.w)));
        acc.x += t0; acc.y += t1; acc.z += t2; acc.w += t3;
    }
    const float sc = 1.0f / K_SAMP;
    float4 o = make_float4(acc.x * sc, acc.y * sc, acc.z * sc, acc.w * sc);
    *(float4*)(out + (size_t)(b0 + w) * E_DIM + lane * 4) = o;
}

// ---------------------------------------------------------------------------
extern "C" void kernel_launch(void* const* d_in, const int* in_sizes, int n_in,
                              void* d_out, int out_size)
{
    const float* features = (const float*)d_in[0];
    const float* W        = (const float*)d_in[1];
    const float* bias     = (const float*)d_in[2];
    const float* gamma    = (const float*)d_in[3];
    const float* beta     = (const float*)d_in[4];
    const int*   sidx     = (const int*)d_in[5];
    float*       out      = (float*)d_out;

    cudaFuncSetAttribute(gemm_mma_kernel,
                         cudaFuncAttributeMaxDynamicSharedMemorySize, SMEM_TOTAL);

    prep_w_kernel<<<128, 256>>>(W);
    gemm_mma_kernel<<<NTILES, 512, SMEM_TOTAL>>>(features, bias);
    finalize_stats_kernel<<<128, 256>>>(gamma, beta);
    gather_mean_kernel<<<B_ROWS / 4, 128>>>(sidx, out);
}